// round 12
// baseline (speedup 1.0000x reference)
#include <cuda_runtime.h>
#include <cuda_fp16.h>
#include <cstdint>
#include <math.h>

#define TSEQ 2048
#define CDIM 1536
#define NH   8
#define KDIM 64
#define VDIM 192
#define HK   512
#define NB   16
#define NQKV 2560   // 512 (Q) + 512 (K) + 1536 (V)
#define LOG2E 1.4426950408889634f

// ====================== scratch (device globals) ===========================
__device__ __align__(256) float g_QKV[(size_t)TSEQ * NQKV];
__device__ float g_P  [(size_t)NH * TSEQ * NB];
__device__ float g_QQ [(size_t)NH * TSEQ * NB];
__device__ float g_U  [NB * HK];
__device__ float g_Vv [NB * HK];
__device__ int   g_lut[TSEQ];

__device__ __align__(256) __half g_x16 [(size_t)TSEQ * CDIM];      // x fp16
__device__ __align__(256) __half g_Wt16[(size_t)NQKV * CDIM];      // Wqkv^T fp16
__device__ __align__(256) __half g_Wo16[(size_t)CDIM * CDIM];      // Wo^T fp16
__device__ __align__(256) __half g_Q16 [(size_t)TSEQ * HK];        // pre-scaled by log2(e)
__device__ __align__(256) __half g_K16 [(size_t)TSEQ * HK];
__device__ __align__(256) __half g_Vt16[(size_t)CDIM * TSEQ];      // V^T [1536][2048]
__device__ __align__(256) __half g_O16 [(size_t)TSEQ * CDIM];      // attn out fp16

// ====================== PTX helpers (baseline-PTX only) ====================
__device__ __forceinline__ uint32_t smem_u32(const void* p) {
    uint32_t a;
    asm("{ .reg .u64 t; cvta.to.shared.u64 t, %1; cvt.u32.u64 %0, t; }" : "=r"(a) : "l"(p));
    return a;
}
__device__ __forceinline__ void cp16(uint32_t dst, const void* src) {
    asm volatile("cp.async.cg.shared.global [%0], [%1], 16;" :: "r"(dst), "l"(src));
}
#define CP_COMMIT() asm volatile("cp.async.commit_group;" ::: "memory")
#define CP_WAIT(n)  asm volatile("cp.async.wait_group %0;" :: "n"(n) : "memory")

__device__ __forceinline__ void ldmx4(uint32_t* r, uint32_t addr) {
    asm volatile("ldmatrix.sync.aligned.m8n8.x4.shared.b16 {%0,%1,%2,%3}, [%4];"
        : "=r"(r[0]), "=r"(r[1]), "=r"(r[2]), "=r"(r[3]) : "r"(addr));
}
__device__ __forceinline__ void mma_fp(float* c, const uint32_t* a, const uint32_t* b) {
    asm volatile(
        "mma.sync.aligned.m16n8k16.row.col.f32.f16.f16.f32 "
        "{%0,%1,%2,%3}, {%4,%5,%6,%7}, {%8,%9}, {%0,%1,%2,%3};"
        : "+f"(c[0]), "+f"(c[1]), "+f"(c[2]), "+f"(c[3])
        : "r"(a[0]), "r"(a[1]), "r"(a[2]), "r"(a[3]), "r"(b[0]), "r"(b[1]));
}
__device__ __forceinline__ float ex2f(float x) {
    float r;
    asm("ex2.approx.f32 %0, %1;" : "=f"(r) : "f"(x));
    return r;
}
// swizzled byte offset within a [rows][32 elem] slab (64B rows, 16B chunks)
__device__ __forceinline__ uint32_t swz(int row, int ck) {
    return (uint32_t)(row * 64 + ((ck ^ ((row >> 1) & 3)) << 4));
}

// ====================== single-pass fp16 HMMA GEMM =========================
// C[m,n] = sum_k A[m,k]*B[n,k]  (both K-major fp16)
template <int BN, int MINB>
__global__ void __launch_bounds__(256, MINB)
gemm_1p(const __half* __restrict__ A, int lda,
        const __half* __restrict__ B, int ldb,
        float* __restrict__ C, int ldc, int Kd, const float* __restrict__ bias)
{
    extern __shared__ char smem[];
    constexpr int MF = 4, NF = BN / 32;
    constexpr int ATILE = 128 * 64, BTILE = BN * 64;
    constexpr int STAGE = ATILE + BTILE;
    constexpr int OFFB  = ATILE;

    const uint32_t sb = smem_u32(smem);
    const int tid = threadIdx.x, lane = tid & 31, wid = tid >> 5;
    const int wm = wid >> 2, wn = wid & 3;
    const int bm = blockIdx.y * 128, bn = blockIdx.x * BN;

    float acc[MF][NF][4];
    #pragma unroll
    for (int i = 0; i < MF; i++)
        #pragma unroll
        for (int j = 0; j < NF; j++)
            #pragma unroll
            for (int t = 0; t < 4; t++) acc[i][j][t] = 0.f;

    auto load_stage = [&](int st, int k0) {
        const uint32_t sa = sb + st * STAGE;
        #pragma unroll
        for (int r = 0; r < 2; r++) {
            int u = tid + r * 256;
            int row = u >> 2, ck = u & 3;
            size_t go = (size_t)(bm + row) * lda + k0 + ck * 8;
            cp16(sa + swz(row, ck), A + go);
        }
        #pragma unroll
        for (int r = 0; r < BN / 64; r++) {
            int u = tid + r * 256;
            int row = u >> 2, ck = u & 3;
            size_t go = (size_t)(bn + row) * ldb + k0 + ck * 8;
            cp16(sa + OFFB + swz(row, ck), B + go);
        }
    };

    auto compute = [&](int st) {
        const uint32_t sa = sb + st * STAGE;
        #pragma unroll
        for (int ks = 0; ks < 2; ks++) {
            uint32_t ah[MF][4];
            const int g = lane >> 3, rr = lane & 7;
            #pragma unroll
            for (int mf = 0; mf < MF; mf++) {
                int row = wm * 64 + mf * 16 + rr + (g & 1) * 8;
                int kc  = ks * 2 + (g >> 1);
                ldmx4(ah[mf], sa + swz(row, kc));
            }
            uint32_t bf[NF][2];
            #pragma unroll
            for (int p = 0; p < NF / 2; p++) {
                int row = wn * (BN / 4) + p * 16 + rr + (g >> 1) * 8;
                int kc  = ks * 2 + (g & 1);
                uint32_t t[4];
                ldmx4(t, sa + OFFB + swz(row, kc));
                bf[2*p][0] = t[0]; bf[2*p][1] = t[1];
                bf[2*p+1][0] = t[2]; bf[2*p+1][1] = t[3];
            }
            #pragma unroll
            for (int mf = 0; mf < MF; mf++)
                #pragma unroll
                for (int nf = 0; nf < NF; nf++)
                    mma_fp(acc[mf][nf], ah[mf], bf[nf]);
        }
    };

    const int NT = Kd >> 5;
    load_stage(0, 0);  CP_COMMIT();
    load_stage(1, 32); CP_COMMIT();

    for (int kt = 0; kt < NT; kt++) {
        CP_WAIT(1);
        __syncthreads();
        compute(kt % 3);
        int nk = kt + 2;
        if (nk < NT) load_stage(nk % 3, nk * 32);
        CP_COMMIT();
    }

    #pragma unroll
    for (int mf = 0; mf < MF; mf++) {
        int r0 = bm + wm * 64 + mf * 16 + (lane >> 2);
        #pragma unroll
        for (int nf = 0; nf < NF; nf++) {
            int c0 = bn + wn * (BN / 4) + nf * 8 + (lane & 3) * 2;
            float2 v0 = make_float2(acc[mf][nf][0], acc[mf][nf][1]);
            float2 v1 = make_float2(acc[mf][nf][2], acc[mf][nf][3]);
            if (bias) {
                float b0 = bias[c0], b1 = bias[c0 + 1];
                v0.x += b0; v0.y += b1; v1.x += b0; v1.y += b1;
            }
            *(float2*)&C[(size_t)r0 * ldc + c0]       = v0;
            *(float2*)&C[(size_t)(r0 + 8) * ldc + c0] = v1;
        }
    }
}

// ====================== fused flash attention ==============================
// CTA = (q-tile of 64 rows, head), 256 threads = 8 warps (2x4 warp grid),
// 64-kv tiles, 32 iterations. 98KB smem -> 2 CTAs/SM. Fixed-shift softmax.
__global__ void __launch_bounds__(256, 2)
flash_kernel()
{
    extern __shared__ char smem[];
    constexpr uint32_t OQ = 0, OKB = 8192, OVB = 24576,
                       OPB = 73728, ORED = 81920, OPT = 83968, OLUTD = 96256;
    const uint32_t sb = smem_u32(smem);
    const int tid = threadIdx.x, lane = tid & 31, wid = tid >> 5;
    const int wm = wid >> 2, wn = wid & 3;                  // 2 x 4 warps
    const int g = lane >> 3, rr = lane & 7, rr4 = lane >> 2, qd = lane & 3;
    const int h = blockIdx.y, bm = blockIdx.x * 64;

    // ---- Q tile load (once): 64 rows x 64 dims fp16, 2 slabs ----
    #pragma unroll
    for (int r = 0; r < 2; r++) {
        int u = tid + r * 256, slab = u >> 8, rem = u & 255, row = rem >> 2, ck = rem & 3;
        size_t go = (size_t)(bm + row) * HK + h * KDIM + slab * 32 + ck * 8;
        cp16(sb + OQ + slab * 4096 + swz(row, ck), g_Q16 + go);
    }
    auto load_kv = [&](int it, int buf) {
        int kvb = it * 64;
        #pragma unroll
        for (int r = 0; r < 2; r++) {       // K: 64 rows x 64 dims, 2 slabs
            int u = tid + r * 256, slab = u >> 8, rem = u & 255, row = rem >> 2, ck = rem & 3;
            size_t go = (size_t)(kvb + row) * HK + h * KDIM + slab * 32 + ck * 8;
            cp16(sb + OKB + buf * 8192 + slab * 4096 + swz(row, ck), g_K16 + go);
        }
        #pragma unroll
        for (int r = 0; r < 6; r++) {       // V^T: 192 rows x 64 kv, 2 slabs
            int u = tid + r * 256, slab = u / 768, rem = u - slab * 768;
            int row = rem >> 2, ck = rem & 3;
            size_t go = (size_t)(h * VDIM + row) * TSEQ + kvb + slab * 32 + ck * 8;
            cp16(sb + OVB + buf * 24576 + slab * 12288 + swz(row, ck), g_Vt16 + go);
        }
    };
    load_kv(0, 0);
    CP_COMMIT();

    // ---- combined bias table Pc[r][48] = log2e*{P-QQ, P, P+QQ} - 4 ----
    float* Pc = (float*)(smem + OPT);
    for (int i = tid; i < 64 * NB; i += 256) {
        int r = i >> 4, m = i & 15;
        float p  = g_P [((size_t)h * TSEQ + bm + r) * NB + m];
        float qq = g_QQ[((size_t)h * TSEQ + bm + r) * NB + m];
        Pc[r * 48 + m]      = (p - qq) * LOG2E - 4.f;
        Pc[r * 48 + 16 + m] = p * LOG2E - 4.f;
        Pc[r * 48 + 32 + m] = (p + qq) * LOG2E - 4.f;
    }
    // signed-distance LUT: d+2048 -> sel*16 + m  (one byte)
    unsigned char* lutD = (unsigned char*)(smem + OLUTD);
    for (int i = tid; i < 4096; i += 256) {
        int dd = i - 2048;
        int ad = dd < 0 ? -dd : dd;
        if (ad > 2047) ad = 2047;
        int m = g_lut[ad];
        int sel = (dd > 0) ? 32 : ((dd < 0) ? 0 : 16);
        lutD[i] = (unsigned char)(sel + m);
    }
    float* red = (float*)(smem + ORED);

    float accO[2][6][4];
    #pragma unroll
    for (int i = 0; i < 2; i++)
        #pragma unroll
        for (int j = 0; j < 6; j++)
            #pragma unroll
            for (int t = 0; t < 4; t++) accO[i][j][t] = 0.f;
    float lsum[2][2];
    lsum[0][0] = lsum[0][1] = lsum[1][0] = lsum[1][1] = 0.f;

    for (int it = 0; it < 32; it++) {
        CP_WAIT(0);
        __syncthreads();            // loads visible; also P-buffer WAR guard
        if (it < 31) { load_kv(it + 1, (it + 1) & 1); CP_COMMIT(); }
        const uint32_t kb  = sb + OKB + (it & 1) * 8192;
        const uint32_t vbs = sb + OVB + (it & 1) * 24576;

        // ---- phase 1: S = Qw . K^T (64x64, fp16, scaled by log2e) ----
        float accS[2][2][4];
        #pragma unroll
        for (int i = 0; i < 2; i++)
            #pragma unroll
            for (int j = 0; j < 2; j++)
                #pragma unroll
                for (int t = 0; t < 4; t++) accS[i][j][t] = 0.f;

        #pragma unroll
        for (int slab = 0; slab < 2; slab++) {
            #pragma unroll
            for (int ks = 0; ks < 2; ks++) {
                uint32_t ah[2][4];
                #pragma unroll
                for (int mf = 0; mf < 2; mf++) {
                    int row = wm * 32 + mf * 16 + rr + (g & 1) * 8;
                    int kc  = ks * 2 + (g >> 1);
                    ldmx4(ah[mf], sb + OQ + slab * 4096 + swz(row, kc));
                }
                uint32_t bf[2][2];
                {
                    int row = wn * 16 + rr + (g >> 1) * 8;
                    int kc  = ks * 2 + (g & 1);
                    uint32_t t[4];
                    ldmx4(t, kb + slab * 4096 + swz(row, kc));
                    bf[0][0] = t[0]; bf[0][1] = t[1];
                    bf[1][0] = t[2]; bf[1][1] = t[3];
                }
                #pragma unroll
                for (int mf = 0; mf < 2; mf++)
                    #pragma unroll
                    for (int nf = 0; nf < 2; nf++)
                        mma_fp(accS[mf][nf], ah[mf], bf[nf]);
            }
        }

        // ---- phase 2: bias + exp2 + partial sum + stage P ----
        #pragma unroll
        for (int mf = 0; mf < 2; mf++)
            #pragma unroll
            for (int hf = 0; hf < 2; hf++) {
                int rloc = wm * 32 + mf * 16 + rr4 + hf * 8;
                const float* Pr = Pc + rloc * 48;
                int base = it * 64 + wn * 16 + qd * 2 - (bm + rloc) + 2048;
                #pragma unroll
                for (int nf = 0; nf < 2; nf++) {
                    int idx = base + nf * 8;
                    float e0 = ex2f(accS[mf][nf][hf*2+0] + Pr[lutD[idx]]);
                    float e1 = ex2f(accS[mf][nf][hf*2+1] + Pr[lutD[idx + 1]]);
                    lsum[mf][hf] += e0 + e1;
                    int jj = wn * 16 + nf * 8 + qd * 2;
                    int slab = jj >> 5, ck = (jj >> 3) & 3;
                    uint32_t off = OPB + slab * 4096 + rloc * 64 +
                                   ((ck ^ ((rloc >> 1) & 3)) << 4) + (jj & 7) * 2;
                    *(__half2*)(smem + off) = __floats2half2_rn(e0, e1);
                }
            }
        __syncthreads();                        // P staging visible

        // ---- phase 3: O += P . V^T ----
        #pragma unroll
        for (int slab = 0; slab < 2; slab++) {
            #pragma unroll
            for (int ks = 0; ks < 2; ks++) {
                uint32_t pa[2][4];
                #pragma unroll
                for (int mf = 0; mf < 2; mf++) {
                    int row = wm * 32 + mf * 16 + rr + (g & 1) * 8;
                    int kc  = ks * 2 + (g >> 1);
                    ldmx4(pa[mf], sb + OPB + slab * 4096 + swz(row, kc));
                }
                uint32_t vf[6][2];
                #pragma unroll
                for (int p = 0; p < 3; p++) {
                    int row = wn * 48 + p * 16 + rr + (g >> 1) * 8;
                    int kc  = ks * 2 + (g & 1);
                    uint32_t t[4];
                    ldmx4(t, vbs + slab * 12288 + swz(row, kc));
                    vf[2*p][0] = t[0]; vf[2*p][1] = t[1];
                    vf[2*p+1][0] = t[2]; vf[2*p+1][1] = t[3];
                }
                #pragma unroll
                for (int mf = 0; mf < 2; mf++)
                    #pragma unroll
                    for (int nf = 0; nf < 6; nf++)
                        mma_fp(accO[mf][nf], pa[mf], vf[nf]);
            }
        }
        // no end-of-iteration sync: loop-top sync orders P rewrite vs reads
    }

    // ---- final: reduce row sums, normalize, write fp16 O ----
    #pragma unroll
    for (int mf = 0; mf < 2; mf++)
        #pragma unroll
        for (int hf = 0; hf < 2; hf++) {
            float s = lsum[mf][hf];
            s += __shfl_xor_sync(0xffffffffu, s, 1);
            s += __shfl_xor_sync(0xffffffffu, s, 2);
            if (qd == 0) {
                int rloc = wm * 32 + mf * 16 + rr4 + hf * 8;
                red[rloc * 4 + wn] = s;
            }
        }
    __syncthreads();
    float inv[2][2];
    #pragma unroll
    for (int mf = 0; mf < 2; mf++)
        #pragma unroll
        for (int hf = 0; hf < 2; hf++) {
            int rloc = wm * 32 + mf * 16 + rr4 + hf * 8;
            inv[mf][hf] = 1.f / (red[rloc*4+0] + red[rloc*4+1] +
                                 red[rloc*4+2] + red[rloc*4+3]);
        }
    #pragma unroll
    for (int mf = 0; mf < 2; mf++) {
        int r0 = bm + wm * 32 + mf * 16 + rr4;
        #pragma unroll
        for (int nf = 0; nf < 6; nf++) {
            int c0 = h * VDIM + wn * 48 + nf * 8 + qd * 2;
            __half2 hh0 = __floats2half2_rn(accO[mf][nf][0] * inv[mf][0],
                                            accO[mf][nf][1] * inv[mf][0]);
            __half2 hh1 = __floats2half2_rn(accO[mf][nf][2] * inv[mf][1],
                                            accO[mf][nf][3] * inv[mf][1]);
            *(__half2*)&g_O16[(size_t)r0 * CDIM + c0]       = hh0;
            *(__half2*)&g_O16[(size_t)(r0 + 8) * CDIM + c0] = hh1;
        }
    }
}

// ====================== fused prep kernels =================================
// prep1: z 0-3 = weight transposes, z=4 = positional setup, z=5 = x->fp16
__global__ void prep1_kernel(const float* __restrict__ Wq, const float* __restrict__ Wk,
                             const float* __restrict__ Wv, const float* __restrict__ Wo,
                             const float* __restrict__ Wr, const float* __restrict__ x)
{
    const int tid = threadIdx.x;
    const int z = blockIdx.z;

    if (z < 4) {
        const float* src; __half* dst; int sld, drow0;
        switch (z) {
            case 0:  src = Wq; dst = g_Wt16; sld = HK;   drow0 = 0;    break;
            case 1:  src = Wk; dst = g_Wt16; sld = HK;   drow0 = 512;  break;
            case 2:  src = Wv; dst = g_Wt16; sld = CDIM; drow0 = 1024; break;
            default: src = Wo; dst = g_Wo16; sld = CDIM; drow0 = 0;    break;
        }
        int n0 = blockIdx.x * 32, k0 = blockIdx.y * 32;
        if (n0 >= sld) return;
        __shared__ float t[32][33];
        int tx = tid & 31, ty = tid >> 5;
        for (int i = ty; i < 32; i += 8)
            t[i][tx] = src[(size_t)(k0 + i) * sld + n0 + tx];
        __syncthreads();
        for (int i = ty; i < 32; i += 8)
            dst[(size_t)(drow0 + n0 + i) * CDIM + k0 + tx] = __float2half(t[tx][i]);
    } else if (z == 4) {
        if (blockIdx.x != 0 || blockIdx.y != 0) return;
        __shared__ float cw[NB];
        if (tid == 0) {
            float pr = expf(logf((float)(TSEQ + 1)) / (float)NB);
            for (int i = 0; i < NB; i++) cw[i] = powf(pr, (float)(i + 1)) - 1.0f;
        }
        __syncthreads();
        for (int d = tid; d < TSEQ; d += 256) {
            int m = 0;
            #pragma unroll
            for (int i = 0; i < NB; i++)
                if (cw[i] <= (float)d) m++;
            g_lut[d] = m;
        }
        for (int c = tid; c < HK; c += 256) {
            float s = 0.f, s2 = 0.f;
            for (int i = NB - 1; i >= 0; i--) {
                s  += Wr[i * HK + c];
                s2 += Wr[(NB + i) * HK + c];
                g_U [i * HK + c] = s;
                g_Vv[i * HK + c] = s2;
            }
        }
    } else {
        // x -> fp16, grid-stride over 48x48 blocks
        size_t base = ((size_t)blockIdx.y * 48 + blockIdx.x) * 256 + tid;
        for (size_t i = base; i < (size_t)TSEQ * CDIM; i += (size_t)48 * 48 * 256)
            g_x16[i] = __float2half(x[i]);
    }
}

// prep2 (after QKV GEMM): z=0 V^T transpose, z=1 Q/K fp16 prep, z=2 pq tables
__global__ void prep2_kernel(const float* __restrict__ rwb, const float* __restrict__ rrb)
{
    const int tid = threadIdx.x;
    const int z = blockIdx.z;
    const int bid = blockIdx.y * 48 + blockIdx.x;

    if (z == 0) {
        // V^T: [2048 tokens][1536 dims(fp32 at QKV col 1024+)] -> [1536][2048] fp16
        __shared__ float t[32][33];
        int n0 = blockIdx.x * 32, k0 = blockIdx.y * 32;   // x<48 dims, y<64 tokens
        int tx = tid & 31, ty = tid >> 5;
        const float* src = g_QKV + 1024;
        for (int i = ty; i < 32; i += 8)
            t[i][tx] = src[(size_t)(k0 + i) * NQKV + n0 + tx];
        __syncthreads();
        for (int i = ty; i < 32; i += 8)
            g_Vt16[(size_t)(n0 + i) * TSEQ + k0 + tx] = __float2half(t[tx][i]);
    } else if (z == 1) {
        for (int i = bid * 256 + tid; i < TSEQ * HK; i += 48 * 64 * 256) {
            int r = i >> 9, c = i & 511;
            g_Q16[i] = __float2half((g_QKV[(size_t)r * NQKV + c] * 0.125f + rwb[c]) * LOG2E);
            g_K16[i] = __float2half(g_QKV[(size_t)r * NQKV + 512 + c]);
        }
    } else {
        // pq: 2 q-rows per 256-thread block
        if (bid >= TSEQ / 2) return;
        __shared__ float qs[2][HK];
        int sub = tid >> 7, t = tid & 127;
        int q = bid * 2 + sub;
        for (int i = t; i < HK; i += 128)
            qs[sub][i] = g_QKV[(size_t)q * NQKV + i] * 0.125f + rrb[i];
        __syncthreads();
        int h = t >> 4, m = t & 15;
        const float* u  = g_U  + m * HK + h * KDIM;
        const float* v2 = g_Vv + m * HK + h * KDIM;
        const float* qh = qs[sub] + h * KDIM;
        float p = 0.f, pq = 0.f;
        #pragma unroll 8
        for (int k = 0; k < KDIM; k++) {
            p  = fmaf(qh[k], u[k],  p);
            pq = fmaf(qh[k], v2[k], pq);
        }
        size_t idx = ((size_t)h * TSEQ + q) * NB + m;
        g_P[idx]  = p;
        g_QQ[idx] = pq;
    }
}

// ====================== launch =============================================
extern "C" void kernel_launch(void* const* d_in, const int* in_sizes, int n_in,
                              void* d_out, int out_size)
{
    const float* x   = (const float*)d_in[0];
    const float* Wq  = (const float*)d_in[1];
    const float* Wk  = (const float*)d_in[2];
    const float* Wv  = (const float*)d_in[3];
    const float* Wr  = (const float*)d_in[4];
    const float* rwb = (const float*)d_in[5];
    const float* rrb = (const float*)d_in[6];
    const float* Wo  = (const float*)d_in[7];
    const float* bo  = (const float*)d_in[8];
    float* out = (float*)d_out;

    float* QKV;
    __half *x16, *Wt16, *Wo16, *O16;
    cudaGetSymbolAddress((void**)&QKV,  g_QKV);
    cudaGetSymbolAddress((void**)&x16,  g_x16);
    cudaGetSymbolAddress((void**)&Wt16, g_Wt16);
    cudaGetSymbolAddress((void**)&Wo16, g_Wo16);
    cudaGetSymbolAddress((void**)&O16,  g_O16);

    constexpr int SMEM_128   = 3 * (8192 + 8192);   // 49152
    constexpr int SMEM_64    = 3 * (8192 + 4096);   // 36864
    constexpr int SMEM_FLASH = 100352;              // 98KB -> 2 CTAs/SM
    cudaFuncSetAttribute((const void*)gemm_1p<128, 1>,
                         cudaFuncAttributeMaxDynamicSharedMemorySize, SMEM_128);
    cudaFuncSetAttribute((const void*)gemm_1p<64, 2>,
                         cudaFuncAttributeMaxDynamicSharedMemorySize, SMEM_64);
    cudaFuncSetAttribute((const void*)flash_kernel,
                         cudaFuncAttributeMaxDynamicSharedMemorySize, SMEM_FLASH);

    // --- fused preprocessing: weight transposes + setup + x conversion ---
    prep1_kernel<<<dim3(48, 48, 6), 256>>>(Wq, Wk, Wv, Wo, Wr, x);

    // --- fused QKV projection (fp16 single-pass) ---
    gemm_1p<128, 1><<<dim3(NQKV / 128, TSEQ / 128, 1), 256, SMEM_128>>>(
        x16, CDIM, Wt16, CDIM, QKV, NQKV, CDIM, nullptr);

    // --- fused post-QKV prep: V^T + Q/K fp16 + pq tables ---
    prep2_kernel<<<dim3(48, 64, 3), 256>>>(rwb, rrb);

    // --- fused attention: 64-row q-tiles, 256 CTAs, 2 CTAs/SM ---
    flash_kernel<<<dim3(TSEQ / 64, NH), 256, SMEM_FLASH>>>();

    // --- output projection: 128x64 tiles (384 CTAs) for wave balance ---
    gemm_1p<64, 2><<<dim3(CDIM / 64, TSEQ / 128, 1), 256, SMEM_64>>>(
        O16, CDIM, Wo16, CDIM, out, CDIM, CDIM, bo);
}

// round 13
// speedup vs baseline: 1.0659x; 1.0659x over previous
#include <cuda_runtime.h>
#include <cuda_fp16.h>
#include <cstdint>
#include <math.h>

#define TSEQ 2048
#define CDIM 1536
#define NH   8
#define KDIM 64
#define VDIM 192
#define HK   512
#define NB   16
#define NQKV 2560   // 512 (Q) + 512 (K) + 1536 (V)
#define LOG2E 1.4426950408889634f

// ====================== scratch (device globals) ===========================
__device__ __align__(256) float g_QKV[(size_t)TSEQ * NQKV];
__device__ float g_P  [(size_t)NH * TSEQ * NB];
__device__ float g_QQ [(size_t)NH * TSEQ * NB];
__device__ float g_U  [NB * HK];
__device__ float g_Vv [NB * HK];
__device__ int   g_lut[TSEQ];

__device__ __align__(256) __half g_x16 [(size_t)TSEQ * CDIM];      // x fp16
__device__ __align__(256) __half g_Wt16[(size_t)NQKV * CDIM];      // Wqkv^T fp16
__device__ __align__(256) __half g_Wo16[(size_t)CDIM * CDIM];      // Wo^T fp16
__device__ __align__(256) __half g_Q16 [(size_t)TSEQ * HK];        // pre-scaled by log2(e)
__device__ __align__(256) __half g_K16 [(size_t)TSEQ * HK];
__device__ __align__(256) __half g_Vt16[(size_t)CDIM * TSEQ];      // V^T [1536][2048]
__device__ __align__(256) __half g_O16 [(size_t)TSEQ * CDIM];      // attn out fp16

// ====================== PTX helpers (baseline-PTX only) ====================
__device__ __forceinline__ uint32_t smem_u32(const void* p) {
    uint32_t a;
    asm("{ .reg .u64 t; cvta.to.shared.u64 t, %1; cvt.u32.u64 %0, t; }" : "=r"(a) : "l"(p));
    return a;
}
__device__ __forceinline__ void cp16(uint32_t dst, const void* src) {
    asm volatile("cp.async.cg.shared.global [%0], [%1], 16;" :: "r"(dst), "l"(src));
}
#define CP_COMMIT() asm volatile("cp.async.commit_group;" ::: "memory")
#define CP_WAIT(n)  asm volatile("cp.async.wait_group %0;" :: "n"(n) : "memory")

__device__ __forceinline__ void ldmx4(uint32_t* r, uint32_t addr) {
    asm volatile("ldmatrix.sync.aligned.m8n8.x4.shared.b16 {%0,%1,%2,%3}, [%4];"
        : "=r"(r[0]), "=r"(r[1]), "=r"(r[2]), "=r"(r[3]) : "r"(addr));
}
__device__ __forceinline__ void mma_fp(float* c, const uint32_t* a, const uint32_t* b) {
    asm volatile(
        "mma.sync.aligned.m16n8k16.row.col.f32.f16.f16.f32 "
        "{%0,%1,%2,%3}, {%4,%5,%6,%7}, {%8,%9}, {%0,%1,%2,%3};"
        : "+f"(c[0]), "+f"(c[1]), "+f"(c[2]), "+f"(c[3])
        : "r"(a[0]), "r"(a[1]), "r"(a[2]), "r"(a[3]), "r"(b[0]), "r"(b[1]));
}
__device__ __forceinline__ float ex2f(float x) {
    float r;
    asm("ex2.approx.f32 %0, %1;" : "=f"(r) : "f"(x));
    return r;
}
// swizzled byte offset within a [rows][32 elem] slab (64B rows, 16B chunks)
__device__ __forceinline__ uint32_t swz(int row, int ck) {
    return (uint32_t)(row * 64 + ((ck ^ ((row >> 1) & 3)) << 4));
}

// ====================== single-pass fp16 HMMA GEMM =========================
// C[m,n] = sum_k A[m,k]*B[n,k]  (both K-major fp16)
// MINB=2 caps regs at 128 -> 2 CTAs/SM co-residency (98KB smem total)
template <int BN, int MINB>
__global__ void __launch_bounds__(256, MINB)
gemm_1p(const __half* __restrict__ A, int lda,
        const __half* __restrict__ B, int ldb,
        float* __restrict__ C, int ldc, int Kd, const float* __restrict__ bias)
{
    extern __shared__ char smem[];
    constexpr int MF = 4, NF = BN / 32;
    constexpr int ATILE = 128 * 64, BTILE = BN * 64;
    constexpr int STAGE = ATILE + BTILE;
    constexpr int OFFB  = ATILE;

    const uint32_t sb = smem_u32(smem);
    const int tid = threadIdx.x, lane = tid & 31, wid = tid >> 5;
    const int wm = wid >> 2, wn = wid & 3;
    const int bm = blockIdx.y * 128, bn = blockIdx.x * BN;

    float acc[MF][NF][4];
    #pragma unroll
    for (int i = 0; i < MF; i++)
        #pragma unroll
        for (int j = 0; j < NF; j++)
            #pragma unroll
            for (int t = 0; t < 4; t++) acc[i][j][t] = 0.f;

    auto load_stage = [&](int st, int k0) {
        const uint32_t sa = sb + st * STAGE;
        #pragma unroll
        for (int r = 0; r < 2; r++) {
            int u = tid + r * 256;
            int row = u >> 2, ck = u & 3;
            size_t go = (size_t)(bm + row) * lda + k0 + ck * 8;
            cp16(sa + swz(row, ck), A + go);
        }
        #pragma unroll
        for (int r = 0; r < BN / 64; r++) {
            int u = tid + r * 256;
            int row = u >> 2, ck = u & 3;
            size_t go = (size_t)(bn + row) * ldb + k0 + ck * 8;
            cp16(sa + OFFB + swz(row, ck), B + go);
        }
    };

    auto compute = [&](int st) {
        const uint32_t sa = sb + st * STAGE;
        #pragma unroll
        for (int ks = 0; ks < 2; ks++) {
            uint32_t ah[MF][4];
            const int g = lane >> 3, rr = lane & 7;
            #pragma unroll
            for (int mf = 0; mf < MF; mf++) {
                int row = wm * 64 + mf * 16 + rr + (g & 1) * 8;
                int kc  = ks * 2 + (g >> 1);
                ldmx4(ah[mf], sa + swz(row, kc));
            }
            uint32_t bf[NF][2];
            #pragma unroll
            for (int p = 0; p < NF / 2; p++) {
                int row = wn * (BN / 4) + p * 16 + rr + (g >> 1) * 8;
                int kc  = ks * 2 + (g & 1);
                uint32_t t[4];
                ldmx4(t, sa + OFFB + swz(row, kc));
                bf[2*p][0] = t[0]; bf[2*p][1] = t[1];
                bf[2*p+1][0] = t[2]; bf[2*p+1][1] = t[3];
            }
            #pragma unroll
            for (int mf = 0; mf < MF; mf++)
                #pragma unroll
                for (int nf = 0; nf < NF; nf++)
                    mma_fp(acc[mf][nf], ah[mf], bf[nf]);
        }
    };

    const int NT = Kd >> 5;
    load_stage(0, 0);  CP_COMMIT();
    load_stage(1, 32); CP_COMMIT();

    for (int kt = 0; kt < NT; kt++) {
        CP_WAIT(1);
        __syncthreads();
        compute(kt % 3);
        int nk = kt + 2;
        if (nk < NT) load_stage(nk % 3, nk * 32);
        CP_COMMIT();
    }

    #pragma unroll
    for (int mf = 0; mf < MF; mf++) {
        int r0 = bm + wm * 64 + mf * 16 + (lane >> 2);
        #pragma unroll
        for (int nf = 0; nf < NF; nf++) {
            int c0 = bn + wn * (BN / 4) + nf * 8 + (lane & 3) * 2;
            float2 v0 = make_float2(acc[mf][nf][0], acc[mf][nf][1]);
            float2 v1 = make_float2(acc[mf][nf][2], acc[mf][nf][3]);
            if (bias) {
                float b0 = bias[c0], b1 = bias[c0 + 1];
                v0.x += b0; v0.y += b1; v1.x += b0; v1.y += b1;
            }
            *(float2*)&C[(size_t)r0 * ldc + c0]       = v0;
            *(float2*)&C[(size_t)(r0 + 8) * ldc + c0] = v1;
        }
    }
}

// ====================== fused flash attention (R11 version) ================
// CTA = (q-tile of 128 rows, head), 512 threads = 16 warps (4x4 warp grid).
// Fixed-shift softmax (no online max); Q & bias tables pre-scaled by log2(e).
__global__ void __launch_bounds__(512, 1)
flash_kernel()
{
    extern __shared__ char smem[];
    constexpr uint32_t OQH = 0,      OKB = 16384,  OVB = 49152,
                       OPB = 147456, ORED = 180224, OPT = 182272, OLUTD = 206848;
    const uint32_t sb = smem_u32(smem);
    const int tid = threadIdx.x, lane = tid & 31, wid = tid >> 5;
    const int wm = wid >> 2, wn = wid & 3;                  // 4 x 4 warps
    const int g = lane >> 3, rr = lane & 7, rr4 = lane >> 2, qd = lane & 3;
    const int h = blockIdx.y, bm = blockIdx.x * 128;

    // ---- Q tile load (once): fp16, 2 slabs ----
    #pragma unroll
    for (int r = 0; r < 2; r++) {
        int u = tid + r * 512, slab = u >> 9, rem = u & 511, row = rem >> 2, ck = rem & 3;
        size_t go = (size_t)(bm + row) * HK + h * KDIM + slab * 32 + ck * 8;
        cp16(sb + OQH + slab * 8192 + swz(row, ck), g_Q16 + go);
    }
    auto load_kv = [&](int it, int buf) {
        int kvb = it * 128;
        #pragma unroll
        for (int r = 0; r < 2; r++) {       // K: 2 slabs x 128 rows
            int u = tid + r * 512, slab = u >> 9, rem = u & 511, row = rem >> 2, ck = rem & 3;
            size_t go = (size_t)(kvb + row) * HK + h * KDIM + slab * 32 + ck * 8;
            cp16(sb + OKB + buf * 16384 + slab * 8192 + swz(row, ck), g_K16 + go);
        }
        #pragma unroll
        for (int r = 0; r < 6; r++) {       // V: 4 slabs x 192 rows
            int u = tid + r * 512, slab = u / 768, rem = u - slab * 768;
            int row = rem >> 2, ck = rem & 3;
            size_t go = (size_t)(h * VDIM + row) * TSEQ + kvb + slab * 32 + ck * 8;
            cp16(sb + OVB + buf * 49152 + slab * 12288 + swz(row, ck), g_Vt16 + go);
        }
    };
    load_kv(0, 0);
    CP_COMMIT();

    // ---- combined bias table Pc[r][48] = log2e*{P-QQ, P, P+QQ} - 4 ----
    float* Pc = (float*)(smem + OPT);
    for (int i = tid; i < 128 * NB; i += 512) {
        int r = i >> 4, m = i & 15;
        float p  = g_P [((size_t)h * TSEQ + bm + r) * NB + m];
        float qq = g_QQ[((size_t)h * TSEQ + bm + r) * NB + m];
        Pc[r * 48 + m]      = (p - qq) * LOG2E - 4.f;
        Pc[r * 48 + 16 + m] = p * LOG2E - 4.f;
        Pc[r * 48 + 32 + m] = (p + qq) * LOG2E - 4.f;
    }
    // signed-distance LUT: d+2048 -> sel*16 + m  (one byte)
    unsigned char* lutD = (unsigned char*)(smem + OLUTD);
    for (int i = tid; i < 4096; i += 512) {
        int dd = i - 2048;
        int ad = dd < 0 ? -dd : dd;
        if (ad > 2047) ad = 2047;
        int m = g_lut[ad];
        int sel = (dd > 0) ? 32 : ((dd < 0) ? 0 : 16);
        lutD[i] = (unsigned char)(sel + m);
    }
    float* red = (float*)(smem + ORED);

    float accO[2][6][4];
    #pragma unroll
    for (int i = 0; i < 2; i++)
        #pragma unroll
        for (int j = 0; j < 6; j++)
            #pragma unroll
            for (int t = 0; t < 4; t++) accO[i][j][t] = 0.f;
    float lsum[2][2];
    lsum[0][0] = lsum[0][1] = lsum[1][0] = lsum[1][1] = 0.f;

    for (int it = 0; it < 16; it++) {
        CP_WAIT(0);
        __syncthreads();            // loads visible; also P-buffer WAR guard
        if (it < 15) { load_kv(it + 1, (it + 1) & 1); CP_COMMIT(); }
        const uint32_t kb  = sb + OKB + (it & 1) * 16384;
        const uint32_t vbs = sb + OVB + (it & 1) * 49152;

        // ---- phase 1: S = Qw . K^T (fp16, result scaled by log2e) ----
        float accS[2][4][4];
        #pragma unroll
        for (int i = 0; i < 2; i++)
            #pragma unroll
            for (int j = 0; j < 4; j++)
                #pragma unroll
                for (int t = 0; t < 4; t++) accS[i][j][t] = 0.f;

        #pragma unroll
        for (int slab = 0; slab < 2; slab++) {
            #pragma unroll
            for (int ks = 0; ks < 2; ks++) {
                uint32_t ah[2][4];
                #pragma unroll
                for (int mf = 0; mf < 2; mf++) {
                    int row = wm * 32 + mf * 16 + rr + (g & 1) * 8;
                    int kc  = ks * 2 + (g >> 1);
                    ldmx4(ah[mf], sb + OQH + slab * 8192 + swz(row, kc));
                }
                uint32_t bf[4][2];
                #pragma unroll
                for (int p = 0; p < 2; p++) {
                    int row = wn * 32 + p * 16 + rr + (g >> 1) * 8;
                    int kc  = ks * 2 + (g & 1);
                    uint32_t t[4];
                    ldmx4(t, kb + slab * 8192 + swz(row, kc));
                    bf[2*p][0] = t[0]; bf[2*p][1] = t[1];
                    bf[2*p+1][0] = t[2]; bf[2*p+1][1] = t[3];
                }
                #pragma unroll
                for (int mf = 0; mf < 2; mf++)
                    #pragma unroll
                    for (int nf = 0; nf < 4; nf++)
                        mma_fp(accS[mf][nf], ah[mf], bf[nf]);
            }
        }

        // ---- phase 2: bias + exp2 + partial sum + stage P ----
        #pragma unroll
        for (int mf = 0; mf < 2; mf++)
            #pragma unroll
            for (int hf = 0; hf < 2; hf++) {
                int rloc = wm * 32 + mf * 16 + rr4 + hf * 8;
                const float* Pr = Pc + rloc * 48;
                int base = it * 128 + wn * 32 + qd * 2 - (bm + rloc) + 2048;
                #pragma unroll
                for (int nf = 0; nf < 4; nf++) {
                    int idx = base + nf * 8;
                    float e0 = ex2f(accS[mf][nf][hf*2+0] + Pr[lutD[idx]]);
                    float e1 = ex2f(accS[mf][nf][hf*2+1] + Pr[lutD[idx + 1]]);
                    lsum[mf][hf] += e0 + e1;
                    int jj = wn * 32 + nf * 8 + qd * 2;
                    int slab = jj >> 5, ck = (jj >> 3) & 3;
                    uint32_t off = OPB + slab * 8192 + rloc * 64 +
                                   ((ck ^ ((rloc >> 1) & 3)) << 4) + (jj & 7) * 2;
                    *(__half2*)(smem + off) = __floats2half2_rn(e0, e1);
                }
            }
        __syncthreads();                        // P staging visible

        // ---- phase 3: O += P . V^T ----
        #pragma unroll
        for (int slab = 0; slab < 4; slab++) {
            #pragma unroll
            for (int ks = 0; ks < 2; ks++) {
                uint32_t pa[2][4];
                #pragma unroll
                for (int mf = 0; mf < 2; mf++) {
                    int row = wm * 32 + mf * 16 + rr + (g & 1) * 8;
                    int kc  = ks * 2 + (g >> 1);
                    ldmx4(pa[mf], sb + OPB + slab * 8192 + swz(row, kc));
                }
                uint32_t vf[6][2];
                #pragma unroll
                for (int p = 0; p < 3; p++) {
                    int row = wn * 48 + p * 16 + rr + (g >> 1) * 8;
                    int kc  = ks * 2 + (g & 1);
                    uint32_t t[4];
                    ldmx4(t, vbs + slab * 12288 + swz(row, kc));
                    vf[2*p][0] = t[0]; vf[2*p][1] = t[1];
                    vf[2*p+1][0] = t[2]; vf[2*p+1][1] = t[3];
                }
                #pragma unroll
                for (int mf = 0; mf < 2; mf++)
                    #pragma unroll
                    for (int nf = 0; nf < 6; nf++)
                        mma_fp(accO[mf][nf], pa[mf], vf[nf]);
            }
        }
        // no end-of-iteration sync: loop-top sync orders P rewrite vs reads
    }

    // ---- final: reduce row sums, normalize, write fp16 O ----
    #pragma unroll
    for (int mf = 0; mf < 2; mf++)
        #pragma unroll
        for (int hf = 0; hf < 2; hf++) {
            float s = lsum[mf][hf];
            s += __shfl_xor_sync(0xffffffffu, s, 1);
            s += __shfl_xor_sync(0xffffffffu, s, 2);
            if (qd == 0) {
                int rloc = wm * 32 + mf * 16 + rr4 + hf * 8;
                red[rloc * 4 + wn] = s;
            }
        }
    __syncthreads();
    float inv[2][2];
    #pragma unroll
    for (int mf = 0; mf < 2; mf++)
        #pragma unroll
        for (int hf = 0; hf < 2; hf++) {
            int rloc = wm * 32 + mf * 16 + rr4 + hf * 8;
            inv[mf][hf] = 1.f / (red[rloc*4+0] + red[rloc*4+1] +
                                 red[rloc*4+2] + red[rloc*4+3]);
        }
    #pragma unroll
    for (int mf = 0; mf < 2; mf++) {
        int r0 = bm + wm * 32 + mf * 16 + rr4;
        #pragma unroll
        for (int nf = 0; nf < 6; nf++) {
            int c0 = h * VDIM + wn * 48 + nf * 8 + qd * 2;
            __half2 hh0 = __floats2half2_rn(accO[mf][nf][0] * inv[mf][0],
                                            accO[mf][nf][1] * inv[mf][0]);
            __half2 hh1 = __floats2half2_rn(accO[mf][nf][2] * inv[mf][1],
                                            accO[mf][nf][3] * inv[mf][1]);
            *(__half2*)&g_O16[(size_t)r0 * CDIM + c0]       = hh0;
            *(__half2*)&g_O16[(size_t)(r0 + 8) * CDIM + c0] = hh1;
        }
    }
}

// ====================== fused prep kernels =================================
// prep1: z 0-3 = weight transposes, z=4 = positional setup, z=5 = x->fp16
__global__ void prep1_kernel(const float* __restrict__ Wq, const float* __restrict__ Wk,
                             const float* __restrict__ Wv, const float* __restrict__ Wo,
                             const float* __restrict__ Wr, const float* __restrict__ x)
{
    const int tid = threadIdx.x;
    const int z = blockIdx.z;

    if (z < 4) {
        const float* src; __half* dst; int sld, drow0;
        switch (z) {
            case 0:  src = Wq; dst = g_Wt16; sld = HK;   drow0 = 0;    break;
            case 1:  src = Wk; dst = g_Wt16; sld = HK;   drow0 = 512;  break;
            case 2:  src = Wv; dst = g_Wt16; sld = CDIM; drow0 = 1024; break;
            default: src = Wo; dst = g_Wo16; sld = CDIM; drow0 = 0;    break;
        }
        int n0 = blockIdx.x * 32, k0 = blockIdx.y * 32;
        if (n0 >= sld) return;
        __shared__ float t[32][33];
        int tx = tid & 31, ty = tid >> 5;
        for (int i = ty; i < 32; i += 8)
            t[i][tx] = src[(size_t)(k0 + i) * sld + n0 + tx];
        __syncthreads();
        for (int i = ty; i < 32; i += 8)
            dst[(size_t)(drow0 + n0 + i) * CDIM + k0 + tx] = __float2half(t[tx][i]);
    } else if (z == 4) {
        if (blockIdx.x != 0 || blockIdx.y != 0) return;
        __shared__ float cw[NB];
        if (tid == 0) {
            float pr = expf(logf((float)(TSEQ + 1)) / (float)NB);
            for (int i = 0; i < NB; i++) cw[i] = powf(pr, (float)(i + 1)) - 1.0f;
        }
        __syncthreads();
        for (int d = tid; d < TSEQ; d += 256) {
            int m = 0;
            #pragma unroll
            for (int i = 0; i < NB; i++)
                if (cw[i] <= (float)d) m++;
            g_lut[d] = m;
        }
        for (int c = tid; c < HK; c += 256) {
            float s = 0.f, s2 = 0.f;
            for (int i = NB - 1; i >= 0; i--) {
                s  += Wr[i * HK + c];
                s2 += Wr[(NB + i) * HK + c];
                g_U [i * HK + c] = s;
                g_Vv[i * HK + c] = s2;
            }
        }
    } else {
        // x -> fp16, grid-stride over 48x48 blocks
        size_t base = ((size_t)blockIdx.y * 48 + blockIdx.x) * 256 + tid;
        for (size_t i = base; i < (size_t)TSEQ * CDIM; i += (size_t)48 * 48 * 256)
            g_x16[i] = __float2half(x[i]);
    }
}

// prep2 (after QKV GEMM): z=0 V^T transpose, z=1 Q/K fp16 prep, z=2 pq tables
__global__ void prep2_kernel(const float* __restrict__ rwb, const float* __restrict__ rrb)
{
    const int tid = threadIdx.x;
    const int z = blockIdx.z;
    const int bid = blockIdx.y * 48 + blockIdx.x;

    if (z == 0) {
        // V^T: [2048 tokens][1536 dims(fp32 at QKV col 1024+)] -> [1536][2048] fp16
        __shared__ float t[32][33];
        int n0 = blockIdx.x * 32, k0 = blockIdx.y * 32;   // x<48 dims, y<64 tokens
        int tx = tid & 31, ty = tid >> 5;
        const float* src = g_QKV + 1024;
        for (int i = ty; i < 32; i += 8)
            t[i][tx] = src[(size_t)(k0 + i) * NQKV + n0 + tx];
        __syncthreads();
        for (int i = ty; i < 32; i += 8)
            g_Vt16[(size_t)(n0 + i) * TSEQ + k0 + tx] = __float2half(t[tx][i]);
    } else if (z == 1) {
        for (int i = bid * 256 + tid; i < TSEQ * HK; i += 48 * 64 * 256) {
            int r = i >> 9, c = i & 511;
            g_Q16[i] = __float2half((g_QKV[(size_t)r * NQKV + c] * 0.125f + rwb[c]) * LOG2E);
            g_K16[i] = __float2half(g_QKV[(size_t)r * NQKV + 512 + c]);
        }
    } else {
        // pq: 2 q-rows per 256-thread block
        if (bid >= TSEQ / 2) return;
        __shared__ float qs[2][HK];
        int sub = tid >> 7, t = tid & 127;
        int q = bid * 2 + sub;
        for (int i = t; i < HK; i += 128)
            qs[sub][i] = g_QKV[(size_t)q * NQKV + i] * 0.125f + rrb[i];
        __syncthreads();
        int h = t >> 4, m = t & 15;
        const float* u  = g_U  + m * HK + h * KDIM;
        const float* v2 = g_Vv + m * HK + h * KDIM;
        const float* qh = qs[sub] + h * KDIM;
        float p = 0.f, pq = 0.f;
        #pragma unroll 8
        for (int k = 0; k < KDIM; k++) {
            p  = fmaf(qh[k], u[k],  p);
            pq = fmaf(qh[k], v2[k], pq);
        }
        size_t idx = ((size_t)h * TSEQ + q) * NB + m;
        g_P[idx]  = p;
        g_QQ[idx] = pq;
    }
}

// ====================== launch =============================================
extern "C" void kernel_launch(void* const* d_in, const int* in_sizes, int n_in,
                              void* d_out, int out_size)
{
    const float* x   = (const float*)d_in[0];
    const float* Wq  = (const float*)d_in[1];
    const float* Wk  = (const float*)d_in[2];
    const float* Wv  = (const float*)d_in[3];
    const float* Wr  = (const float*)d_in[4];
    const float* rwb = (const float*)d_in[5];
    const float* rrb = (const float*)d_in[6];
    const float* Wo  = (const float*)d_in[7];
    const float* bo  = (const float*)d_in[8];
    float* out = (float*)d_out;

    float* QKV;
    __half *x16, *Wt16, *Wo16, *O16;
    cudaGetSymbolAddress((void**)&QKV,  g_QKV);
    cudaGetSymbolAddress((void**)&x16,  g_x16);
    cudaGetSymbolAddress((void**)&Wt16, g_Wt16);
    cudaGetSymbolAddress((void**)&Wo16, g_Wo16);
    cudaGetSymbolAddress((void**)&O16,  g_O16);

    constexpr int SMEM_128   = 3 * (8192 + 8192);   // 49152 -> 2 CTAs/SM with MINB=2
    constexpr int SMEM_64    = 3 * (8192 + 4096);   // 36864
    constexpr int SMEM_FLASH = 210944;
    cudaFuncSetAttribute((const void*)gemm_1p<128, 2>,
                         cudaFuncAttributeMaxDynamicSharedMemorySize, SMEM_128);
    cudaFuncSetAttribute((const void*)gemm_1p<64, 2>,
                         cudaFuncAttributeMaxDynamicSharedMemorySize, SMEM_64);
    cudaFuncSetAttribute((const void*)flash_kernel,
                         cudaFuncAttributeMaxDynamicSharedMemorySize, SMEM_FLASH);

    // --- fused preprocessing: weight transposes + setup + x conversion ---
    prep1_kernel<<<dim3(48, 48, 6), 256>>>(Wq, Wk, Wv, Wo, Wr, x);

    // --- fused QKV projection (fp16 single-pass, 2 CTAs/SM) ---
    gemm_1p<128, 2><<<dim3(NQKV / 128, TSEQ / 128, 1), 256, SMEM_128>>>(
        x16, CDIM, Wt16, CDIM, QKV, NQKV, CDIM, nullptr);

    // --- fused post-QKV prep: V^T + Q/K fp16 + pq tables ---
    prep2_kernel<<<dim3(48, 64, 3), 256>>>(rwb, rrb);

    // --- fused attention: 128-row q-tiles (R11 config) ---
    flash_kernel<<<dim3(TSEQ / 128, NH), 512, SMEM_FLASH>>>();

    // --- output projection: 128x64 tiles (384 CTAs, 2 CTAs/SM) ---
    gemm_1p<64, 2><<<dim3(CDIM / 64, TSEQ / 128, 1), 256, SMEM_64>>>(
        O16, CDIM, Wo16, CDIM, out, CDIM, CDIM, bo);
}

// round 15
// speedup vs baseline: 1.0905x; 1.0231x over previous
#include <cuda_runtime.h>
#include <cuda_fp16.h>
#include <cstdint>
#include <math.h>

#define TSEQ 2048
#define CDIM 1536
#define NH   8
#define KDIM 64
#define VDIM 192
#define HK   512
#define NB   16
#define NQKV 2560   // 512 (Q) + 512 (K) + 1536 (V)
#define LOG2E 1.4426950408889634f
#define PCW  52     // Pc row stride (floats), padded for bank spread

// ====================== scratch (device globals) ===========================
__device__ __align__(256) float g_QKV[(size_t)TSEQ * NQKV];
__device__ float g_P  [(size_t)NH * TSEQ * NB];
__device__ float g_QQ [(size_t)NH * TSEQ * NB];
__device__ float g_U  [NB * HK];
__device__ float g_Vv [NB * HK];
__device__ int   g_lut[TSEQ];

__device__ __align__(256) __half g_x16 [(size_t)TSEQ * CDIM];      // x fp16
__device__ __align__(256) __half g_Wt16[(size_t)NQKV * CDIM];      // Wqkv^T fp16
__device__ __align__(256) __half g_Wo16[(size_t)CDIM * CDIM];      // Wo^T fp16
__device__ __align__(256) __half g_Q16 [(size_t)TSEQ * HK];        // pre-scaled by log2(e)
__device__ __align__(256) __half g_K16 [(size_t)TSEQ * HK];
__device__ __align__(256) __half g_Vt16[(size_t)CDIM * TSEQ];      // V^T [1536][2048]
__device__ __align__(256) __half g_O16 [(size_t)TSEQ * CDIM];      // attn out fp16

// ====================== PTX helpers (baseline-PTX only) ====================
__device__ __forceinline__ uint32_t smem_u32(const void* p) {
    uint32_t a;
    asm("{ .reg .u64 t; cvta.to.shared.u64 t, %1; cvt.u32.u64 %0, t; }" : "=r"(a) : "l"(p));
    return a;
}
__device__ __forceinline__ void cp16(uint32_t dst, const void* src) {
    asm volatile("cp.async.cg.shared.global [%0], [%1], 16;" :: "r"(dst), "l"(src));
}
#define CP_COMMIT() asm volatile("cp.async.commit_group;" ::: "memory")
#define CP_WAIT(n)  asm volatile("cp.async.wait_group %0;" :: "n"(n) : "memory")

__device__ __forceinline__ void ldmx4(uint32_t* r, uint32_t addr) {
    asm volatile("ldmatrix.sync.aligned.m8n8.x4.shared.b16 {%0,%1,%2,%3}, [%4];"
        : "=r"(r[0]), "=r"(r[1]), "=r"(r[2]), "=r"(r[3]) : "r"(addr));
}
__device__ __forceinline__ void mma_fp(float* c, const uint32_t* a, const uint32_t* b) {
    asm volatile(
        "mma.sync.aligned.m16n8k16.row.col.f32.f16.f16.f32 "
        "{%0,%1,%2,%3}, {%4,%5,%6,%7}, {%8,%9}, {%0,%1,%2,%3};"
        : "+f"(c[0]), "+f"(c[1]), "+f"(c[2]), "+f"(c[3])
        : "r"(a[0]), "r"(a[1]), "r"(a[2]), "r"(a[3]), "r"(b[0]), "r"(b[1]));
}
__device__ __forceinline__ float ex2f(float x) {
    float r;
    asm("ex2.approx.f32 %0, %1;" : "=f"(r) : "f"(x));
    return r;
}
// swizzled byte offset within a [rows][32 elem] slab (64B rows, 16B chunks)
__device__ __forceinline__ uint32_t swz(int row, int ck) {
    return (uint32_t)(row * 64 + ((ck ^ ((row >> 1) & 3)) << 4));
}

// ====================== single-pass fp16 HMMA GEMM =========================
// C[m,n] = sum_k A[m,k]*B[n,k]  (both K-major fp16)
// QKEPI: fused epilogue writing g_Q16/g_K16 for columns < 1024 (QKV launch)
template <int BN, int MINB, bool QKEPI>
__global__ void __launch_bounds__(256, MINB)
gemm_1p(const __half* __restrict__ A, int lda,
        const __half* __restrict__ B, int ldb,
        float* __restrict__ C, int ldc, int Kd, const float* __restrict__ bias,
        const float* __restrict__ rwb)
{
    extern __shared__ char smem[];
    constexpr int MF = 4, NF = BN / 32;
    constexpr int ATILE = 128 * 64, BTILE = BN * 64;
    constexpr int STAGE = ATILE + BTILE;
    constexpr int OFFB  = ATILE;

    const uint32_t sb = smem_u32(smem);
    const int tid = threadIdx.x, lane = tid & 31, wid = tid >> 5;
    const int wm = wid >> 2, wn = wid & 3;
    const int bm = blockIdx.y * 128, bn = blockIdx.x * BN;

    float acc[MF][NF][4];
    #pragma unroll
    for (int i = 0; i < MF; i++)
        #pragma unroll
        for (int j = 0; j < NF; j++)
            #pragma unroll
            for (int t = 0; t < 4; t++) acc[i][j][t] = 0.f;

    auto load_stage = [&](int st, int k0) {
        const uint32_t sa = sb + st * STAGE;
        #pragma unroll
        for (int r = 0; r < 2; r++) {
            int u = tid + r * 256;
            int row = u >> 2, ck = u & 3;
            size_t go = (size_t)(bm + row) * lda + k0 + ck * 8;
            cp16(sa + swz(row, ck), A + go);
        }
        #pragma unroll
        for (int r = 0; r < BN / 64; r++) {
            int u = tid + r * 256;
            int row = u >> 2, ck = u & 3;
            size_t go = (size_t)(bn + row) * ldb + k0 + ck * 8;
            cp16(sa + OFFB + swz(row, ck), B + go);
        }
    };

    auto compute = [&](int st) {
        const uint32_t sa = sb + st * STAGE;
        #pragma unroll
        for (int ks = 0; ks < 2; ks++) {
            uint32_t ah[MF][4];
            const int g = lane >> 3, rr = lane & 7;
            #pragma unroll
            for (int mf = 0; mf < MF; mf++) {
                int row = wm * 64 + mf * 16 + rr + (g & 1) * 8;
                int kc  = ks * 2 + (g >> 1);
                ldmx4(ah[mf], sa + swz(row, kc));
            }
            uint32_t bf[NF][2];
            #pragma unroll
            for (int p = 0; p < NF / 2; p++) {
                int row = wn * (BN / 4) + p * 16 + rr + (g >> 1) * 8;
                int kc  = ks * 2 + (g & 1);
                uint32_t t[4];
                ldmx4(t, sa + OFFB + swz(row, kc));
                bf[2*p][0] = t[0]; bf[2*p][1] = t[1];
                bf[2*p+1][0] = t[2]; bf[2*p+1][1] = t[3];
            }
            #pragma unroll
            for (int mf = 0; mf < MF; mf++)
                #pragma unroll
                for (int nf = 0; nf < NF; nf++)
                    mma_fp(acc[mf][nf], ah[mf], bf[nf]);
        }
    };

    const int NT = Kd >> 5;
    load_stage(0, 0);  CP_COMMIT();
    load_stage(1, 32); CP_COMMIT();

    for (int kt = 0; kt < NT; kt++) {
        CP_WAIT(1);
        __syncthreads();
        compute(kt % 3);
        int nk = kt + 2;
        if (nk < NT) load_stage(nk % 3, nk * 32);
        CP_COMMIT();
    }

    #pragma unroll
    for (int mf = 0; mf < MF; mf++) {
        int r0 = bm + wm * 64 + mf * 16 + (lane >> 2);
        #pragma unroll
        for (int nf = 0; nf < NF; nf++) {
            int c0 = bn + wn * (BN / 4) + nf * 8 + (lane & 3) * 2;
            float2 v0 = make_float2(acc[mf][nf][0], acc[mf][nf][1]);
            float2 v1 = make_float2(acc[mf][nf][2], acc[mf][nf][3]);
            if (bias) {
                float b0 = bias[c0], b1 = bias[c0 + 1];
                v0.x += b0; v0.y += b1; v1.x += b0; v1.y += b1;
            }
            *(float2*)&C[(size_t)r0 * ldc + c0]       = v0;
            *(float2*)&C[(size_t)(r0 + 8) * ldc + c0] = v1;
            if (QKEPI && c0 < 1024) {
                if (c0 < 512) {       // Q region: scale + r_w_bias + log2e
                    float b0 = rwb[c0], b1 = rwb[c0 + 1];
                    __half2 q0 = __floats2half2_rn((v0.x * 0.125f + b0) * LOG2E,
                                                   (v0.y * 0.125f + b1) * LOG2E);
                    __half2 q1 = __floats2half2_rn((v1.x * 0.125f + b0) * LOG2E,
                                                   (v1.y * 0.125f + b1) * LOG2E);
                    *(__half2*)&g_Q16[(size_t)r0 * HK + c0]       = q0;
                    *(__half2*)&g_Q16[(size_t)(r0 + 8) * HK + c0] = q1;
                } else {              // K region
                    int ck0 = c0 - 512;
                    *(__half2*)&g_K16[(size_t)r0 * HK + ck0]       = __floats2half2_rn(v0.x, v0.y);
                    *(__half2*)&g_K16[(size_t)(r0 + 8) * HK + ck0] = __floats2half2_rn(v1.x, v1.y);
                }
            }
        }
    }
}

// ====================== fused flash attention ==============================
// CTA = (q-tile of 128 rows, head), 512 threads = 16 warps (4x4 warp grid).
// Fixed-shift softmax (no online max); Q & bias tables pre-scaled by log2(e).
__global__ void __launch_bounds__(512, 1)
flash_kernel()
{
    extern __shared__ char smem[];
    // layout: Q 16384 | K 2x16384 | V 2x49152 | P 32768 | red 2048 |
    //         Pc 128*PCW*4 = 26624 | lutD 4096  -> total 214016
    constexpr uint32_t OQH = 0,      OKB = 16384,  OVB = 49152,
                       OPB = 147456, ORED = 180224, OPT = 182272, OLUTD = 208896;
    const uint32_t sb = smem_u32(smem);
    const int tid = threadIdx.x, lane = tid & 31, wid = tid >> 5;
    const int wm = wid >> 2, wn = wid & 3;                  // 4 x 4 warps
    const int g = lane >> 3, rr = lane & 7, rr4 = lane >> 2, qd = lane & 3;
    const int h = blockIdx.y, bm = blockIdx.x * 128;

    // ---- Q tile load (once): fp16, 2 slabs ----
    #pragma unroll
    for (int r = 0; r < 2; r++) {
        int u = tid + r * 512, slab = u >> 9, rem = u & 511, row = rem >> 2, ck = rem & 3;
        size_t go = (size_t)(bm + row) * HK + h * KDIM + slab * 32 + ck * 8;
        cp16(sb + OQH + slab * 8192 + swz(row, ck), g_Q16 + go);
    }
    auto load_kv = [&](int it, int buf) {
        int kvb = it * 128;
        #pragma unroll
        for (int r = 0; r < 2; r++) {       // K: 2 slabs x 128 rows
            int u = tid + r * 512, slab = u >> 9, rem = u & 511, row = rem >> 2, ck = rem & 3;
            size_t go = (size_t)(kvb + row) * HK + h * KDIM + slab * 32 + ck * 8;
            cp16(sb + OKB + buf * 16384 + slab * 8192 + swz(row, ck), g_K16 + go);
        }
        #pragma unroll
        for (int r = 0; r < 6; r++) {       // V: 4 slabs x 192 rows
            int u = tid + r * 512, slab = u / 768, rem = u - slab * 768;
            int row = rem >> 2, ck = rem & 3;
            size_t go = (size_t)(h * VDIM + row) * TSEQ + kvb + slab * 32 + ck * 8;
            cp16(sb + OVB + buf * 49152 + slab * 12288 + swz(row, ck), g_Vt16 + go);
        }
    };
    load_kv(0, 0);
    CP_COMMIT();

    // ---- combined bias table Pc[r][PCW] = log2e*{P-QQ, P, P+QQ} - 4 ----
    float* Pc = (float*)(smem + OPT);
    for (int i = tid; i < 128 * NB; i += 512) {
        int r = i >> 4, m = i & 15;
        float p  = g_P [((size_t)h * TSEQ + bm + r) * NB + m];
        float qq = g_QQ[((size_t)h * TSEQ + bm + r) * NB + m];
        Pc[r * PCW + m]      = (p - qq) * LOG2E - 4.f;
        Pc[r * PCW + 16 + m] = p * LOG2E - 4.f;
        Pc[r * PCW + 32 + m] = (p + qq) * LOG2E - 4.f;
    }
    // signed-distance LUT: d+2048 -> sel*16 + m  (one byte)
    unsigned char* lutD = (unsigned char*)(smem + OLUTD);
    for (int i = tid; i < 4096; i += 512) {
        int dd = i - 2048;
        int ad = dd < 0 ? -dd : dd;
        if (ad > 2047) ad = 2047;
        int m = g_lut[ad];
        int sel = (dd > 0) ? 32 : ((dd < 0) ? 0 : 16);
        lutD[i] = (unsigned char)(sel + m);
    }
    float* red = (float*)(smem + ORED);

    float accO[2][6][4];
    #pragma unroll
    for (int i = 0; i < 2; i++)
        #pragma unroll
        for (int j = 0; j < 6; j++)
            #pragma unroll
            for (int t = 0; t < 4; t++) accO[i][j][t] = 0.f;
    float lsum[2][2];
    lsum[0][0] = lsum[0][1] = lsum[1][0] = lsum[1][1] = 0.f;

    for (int it = 0; it < 16; it++) {
        CP_WAIT(0);
        __syncthreads();            // loads visible; also P-buffer WAR guard
        if (it < 15) { load_kv(it + 1, (it + 1) & 1); CP_COMMIT(); }
        const uint32_t kb  = sb + OKB + (it & 1) * 16384;
        const uint32_t vbs = sb + OVB + (it & 1) * 49152;

        // ---- phase 1: S = Qw . K^T (fp16, result scaled by log2e) ----
        float accS[2][4][4];
        #pragma unroll
        for (int i = 0; i < 2; i++)
            #pragma unroll
            for (int j = 0; j < 4; j++)
                #pragma unroll
                for (int t = 0; t < 4; t++) accS[i][j][t] = 0.f;

        #pragma unroll
        for (int slab = 0; slab < 2; slab++) {
            #pragma unroll
            for (int ks = 0; ks < 2; ks++) {
                uint32_t ah[2][4];
                #pragma unroll
                for (int mf = 0; mf < 2; mf++) {
                    int row = wm * 32 + mf * 16 + rr + (g & 1) * 8;
                    int kc  = ks * 2 + (g >> 1);
                    ldmx4(ah[mf], sb + OQH + slab * 8192 + swz(row, kc));
                }
                uint32_t bf[4][2];
                #pragma unroll
                for (int p = 0; p < 2; p++) {
                    int row = wn * 32 + p * 16 + rr + (g >> 1) * 8;
                    int kc  = ks * 2 + (g & 1);
                    uint32_t t[4];
                    ldmx4(t, kb + slab * 8192 + swz(row, kc));
                    bf[2*p][0] = t[0]; bf[2*p][1] = t[1];
                    bf[2*p+1][0] = t[2]; bf[2*p+1][1] = t[3];
                }
                #pragma unroll
                for (int mf = 0; mf < 2; mf++)
                    #pragma unroll
                    for (int nf = 0; nf < 4; nf++)
                        mma_fp(accS[mf][nf], ah[mf], bf[nf]);
            }
        }

        // ---- phase 2: bias + exp2 + partial sum + stage P ----
        #pragma unroll
        for (int mf = 0; mf < 2; mf++)
            #pragma unroll
            for (int hf = 0; hf < 2; hf++) {
                int rloc = wm * 32 + mf * 16 + rr4 + hf * 8;
                const float* Pr = Pc + rloc * PCW;
                int base = it * 128 + wn * 32 + qd * 2 - (bm + rloc) + 2048;
                #pragma unroll
                for (int nf = 0; nf < 4; nf++) {
                    int idx = base + nf * 8;
                    float e0 = ex2f(accS[mf][nf][hf*2+0] + Pr[lutD[idx]]);
                    float e1 = ex2f(accS[mf][nf][hf*2+1] + Pr[lutD[idx + 1]]);
                    lsum[mf][hf] += e0 + e1;
                    int jj = wn * 32 + nf * 8 + qd * 2;
                    int slab = jj >> 5, ck = (jj >> 3) & 3;
                    uint32_t off = OPB + slab * 8192 + rloc * 64 +
                                   ((ck ^ ((rloc >> 1) & 3)) << 4) + (jj & 7) * 2;
                    *(__half2*)(smem + off) = __floats2half2_rn(e0, e1);
                }
            }
        __syncthreads();                        // P staging visible

        // ---- phase 3: O += P . V^T ----
        #pragma unroll
        for (int slab = 0; slab < 4; slab++) {
            #pragma unroll
            for (int ks = 0; ks < 2; ks++) {
                uint32_t pa[2][4];
                #pragma unroll
                for (int mf = 0; mf < 2; mf++) {
                    int row = wm * 32 + mf * 16 + rr + (g & 1) * 8;
                    int kc  = ks * 2 + (g >> 1);
                    ldmx4(pa[mf], sb + OPB + slab * 8192 + swz(row, kc));
                }
                uint32_t vf[6][2];
                #pragma unroll
                for (int p = 0; p < 3; p++) {
                    int row = wn * 48 + p * 16 + rr + (g >> 1) * 8;
                    int kc  = ks * 2 + (g & 1);
                    uint32_t t[4];
                    ldmx4(t, vbs + slab * 12288 + swz(row, kc));
                    vf[2*p][0] = t[0]; vf[2*p][1] = t[1];
                    vf[2*p+1][0] = t[2]; vf[2*p+1][1] = t[3];
                }
                #pragma unroll
                for (int mf = 0; mf < 2; mf++)
                    #pragma unroll
                    for (int nf = 0; nf < 6; nf++)
                        mma_fp(accO[mf][nf], pa[mf], vf[nf]);
            }
        }
        // no end-of-iteration sync: loop-top sync orders P rewrite vs reads
    }

    // ---- final: reduce row sums, normalize, write fp16 O ----
    #pragma unroll
    for (int mf = 0; mf < 2; mf++)
        #pragma unroll
        for (int hf = 0; hf < 2; hf++) {
            float s = lsum[mf][hf];
            s += __shfl_xor_sync(0xffffffffu, s, 1);
            s += __shfl_xor_sync(0xffffffffu, s, 2);
            if (qd == 0) {
                int rloc = wm * 32 + mf * 16 + rr4 + hf * 8;
                red[rloc * 4 + wn] = s;
            }
        }
    __syncthreads();
    float inv[2][2];
    #pragma unroll
    for (int mf = 0; mf < 2; mf++)
        #pragma unroll
        for (int hf = 0; hf < 2; hf++) {
            int rloc = wm * 32 + mf * 16 + rr4 + hf * 8;
            inv[mf][hf] = 1.f / (red[rloc*4+0] + red[rloc*4+1] +
                                 red[rloc*4+2] + red[rloc*4+3]);
        }
    #pragma unroll
    for (int mf = 0; mf < 2; mf++) {
        int r0 = bm + wm * 32 + mf * 16 + rr4;
        #pragma unroll
        for (int nf = 0; nf < 6; nf++) {
            int c0 = h * VDIM + wn * 48 + nf * 8 + qd * 2;
            __half2 hh0 = __floats2half2_rn(accO[mf][nf][0] * inv[mf][0],
                                            accO[mf][nf][1] * inv[mf][0]);
            __half2 hh1 = __floats2half2_rn(accO[mf][nf][2] * inv[mf][1],
                                            accO[mf][nf][3] * inv[mf][1]);
            *(__half2*)&g_O16[(size_t)r0 * CDIM + c0]       = hh0;
            *(__half2*)&g_O16[(size_t)(r0 + 8) * CDIM + c0] = hh1;
        }
    }
}

// ====================== fused prep kernels =================================
// prep1: z 0-3 = weight transposes, z=4 = positional setup, z=5 = x->fp16
__global__ void prep1_kernel(const float* __restrict__ Wq, const float* __restrict__ Wk,
                             const float* __restrict__ Wv, const float* __restrict__ Wo,
                             const float* __restrict__ Wr, const float* __restrict__ x)
{
    const int tid = threadIdx.x;
    const int z = blockIdx.z;

    if (z < 4) {
        const float* src; __half* dst; int sld, drow0;
        switch (z) {
            case 0:  src = Wq; dst = g_Wt16; sld = HK;   drow0 = 0;    break;
            case 1:  src = Wk; dst = g_Wt16; sld = HK;   drow0 = 512;  break;
            case 2:  src = Wv; dst = g_Wt16; sld = CDIM; drow0 = 1024; break;
            default: src = Wo; dst = g_Wo16; sld = CDIM; drow0 = 0;    break;
        }
        int n0 = blockIdx.x * 32, k0 = blockIdx.y * 32;
        if (n0 >= sld) return;
        __shared__ float t[32][33];
        int tx = tid & 31, ty = tid >> 5;
        for (int i = ty; i < 32; i += 8)
            t[i][tx] = src[(size_t)(k0 + i) * sld + n0 + tx];
        __syncthreads();
        for (int i = ty; i < 32; i += 8)
            dst[(size_t)(drow0 + n0 + i) * CDIM + k0 + tx] = __float2half(t[tx][i]);
    } else if (z == 4) {
        if (blockIdx.x != 0 || blockIdx.y != 0) return;
        __shared__ float cw[NB];
        if (tid == 0) {
            float pr = expf(logf((float)(TSEQ + 1)) / (float)NB);
            for (int i = 0; i < NB; i++) cw[i] = powf(pr, (float)(i + 1)) - 1.0f;
        }
        __syncthreads();
        for (int d = tid; d < TSEQ; d += 256) {
            int m = 0;
            #pragma unroll
            for (int i = 0; i < NB; i++)
                if (cw[i] <= (float)d) m++;
            g_lut[d] = m;
        }
        for (int c = tid; c < HK; c += 256) {
            float s = 0.f, s2 = 0.f;
            for (int i = NB - 1; i >= 0; i--) {
                s  += Wr[i * HK + c];
                s2 += Wr[(NB + i) * HK + c];
                g_U [i * HK + c] = s;
                g_Vv[i * HK + c] = s2;
            }
        }
    } else {
        // x -> fp16, grid-stride over 48x48 blocks
        size_t base = ((size_t)blockIdx.y * 48 + blockIdx.x) * 256 + tid;
        for (size_t i = base; i < (size_t)TSEQ * CDIM; i += (size_t)48 * 48 * 256)
            g_x16[i] = __float2half(x[i]);
    }
}

// prep2 (after QKV GEMM): z=0 V^T transpose, z=1 pq tables
__global__ void prep2_kernel(const float* __restrict__ rrb)
{
    const int tid = threadIdx.x;
    const int z = blockIdx.z;
    const int bid = blockIdx.y * 48 + blockIdx.x;

    if (z == 0) {
        // V^T: [2048 tokens][1536 dims(fp32 at QKV col 1024+)] -> [1536][2048] fp16
        __shared__ float t[32][33];
        int n0 = blockIdx.x * 32, k0 = blockIdx.y * 32;   // x<48 dims, y<64 tokens
        int tx = tid & 31, ty = tid >> 5;
        const float* src = g_QKV + 1024;
        for (int i = ty; i < 32; i += 8)
            t[i][tx] = src[(size_t)(k0 + i) * NQKV + n0 + tx];
        __syncthreads();
        for (int i = ty; i < 32; i += 8)
            g_Vt16[(size_t)(n0 + i) * TSEQ + k0 + tx] = __float2half(t[tx][i]);
    } else {
        // pq: 2 q-rows per 256-thread block
        if (bid >= TSEQ / 2) return;
        __shared__ float qs[2][HK];
        int sub = tid >> 7, t = tid & 127;
        int q = bid * 2 + sub;
        for (int i = t; i < HK; i += 128)
            qs[sub][i] = g_QKV[(size_t)q * NQKV + i] * 0.125f + rrb[i];
        __syncthreads();
        int h = t >> 4, m = t & 15;
        const float* u  = g_U  + m * HK + h * KDIM;
        const float* v2 = g_Vv + m * HK + h * KDIM;
        const float* qh = qs[sub] + h * KDIM;
        float p = 0.f, pq = 0.f;
        #pragma unroll 8
        for (int k = 0; k < KDIM; k++) {
            p  = fmaf(qh[k], u[k],  p);
            pq = fmaf(qh[k], v2[k], pq);
        }
        size_t idx = ((size_t)h * TSEQ + q) * NB + m;
        g_P[idx]  = p;
        g_QQ[idx] = pq;
    }
}

// ====================== launch =============================================
extern "C" void kernel_launch(void* const* d_in, const int* in_sizes, int n_in,
                              void* d_out, int out_size)
{
    const float* x   = (const float*)d_in[0];
    const float* Wq  = (const float*)d_in[1];
    const float* Wk  = (const float*)d_in[2];
    const float* Wv  = (const float*)d_in[3];
    const float* Wr  = (const float*)d_in[4];
    const float* rwb = (const float*)d_in[5];
    const float* rrb = (const float*)d_in[6];
    const float* Wo  = (const float*)d_in[7];
    const float* bo  = (const float*)d_in[8];
    float* out = (float*)d_out;

    float* QKV;
    __half *x16, *Wt16, *Wo16, *O16;
    cudaGetSymbolAddress((void**)&QKV,  g_QKV);
    cudaGetSymbolAddress((void**)&x16,  g_x16);
    cudaGetSymbolAddress((void**)&Wt16, g_Wt16);
    cudaGetSymbolAddress((void**)&Wo16, g_Wo16);
    cudaGetSymbolAddress((void**)&O16,  g_O16);

    constexpr int SMEM_128   = 3 * (8192 + 8192);   // 49152 -> 2 CTAs/SM with MINB=2
    constexpr int SMEM_64    = 3 * (8192 + 4096);   // 36864
    constexpr int SMEM_FLASH = 214528;              // lutD ends at 212992; headroom
    cudaFuncSetAttribute((const void*)gemm_1p<128, 2, true>,
                         cudaFuncAttributeMaxDynamicSharedMemorySize, SMEM_128);
    cudaFuncSetAttribute((const void*)gemm_1p<64, 2, false>,
                         cudaFuncAttributeMaxDynamicSharedMemorySize, SMEM_64);
    cudaFuncSetAttribute((const void*)flash_kernel,
                         cudaFuncAttributeMaxDynamicSharedMemorySize, SMEM_FLASH);

    // --- fused preprocessing: weight transposes + setup + x conversion ---
    prep1_kernel<<<dim3(48, 48, 6), 256>>>(Wq, Wk, Wv, Wo, Wr, x);

    // --- fused QKV projection + Q16/K16 epilogue (fp16 single-pass) ---
    gemm_1p<128, 2, true><<<dim3(NQKV / 128, TSEQ / 128, 1), 256, SMEM_128>>>(
        x16, CDIM, Wt16, CDIM, QKV, NQKV, CDIM, nullptr, rwb);

    // --- fused post-QKV prep: V^T + pq tables ---
    prep2_kernel<<<dim3(48, 64, 2), 256>>>(rrb);

    // --- fused attention: 128-row q-tiles (Pc bank padding) ---
    flash_kernel<<<dim3(TSEQ / 128, NH), 512, SMEM_FLASH>>>();

    // --- output projection: 128x64 tiles (384 CTAs, 2 CTAs/SM) ---
    gemm_1p<64, 2, false><<<dim3(CDIM / 64, TSEQ / 128, 1), 256, SMEM_64>>>(
        O16, CDIM, Wo16, CDIM, out, CDIM, CDIM, bo, nullptr);
}

// round 16
// speedup vs baseline: 1.1274x; 1.0338x over previous
#include <cuda_runtime.h>
#include <cuda_fp16.h>
#include <cstdint>
#include <math.h>

#define TSEQ 2048
#define CDIM 1536
#define NH   8
#define KDIM 64
#define VDIM 192
#define HK   512
#define NB   16
#define NQKV 2560   // 512 (Q) + 512 (K) + 1536 (V)
#define LOG2E 1.4426950408889634f
#define PCW  52     // Pc row stride (floats), padded for bank spread

// ====================== scratch (device globals) ===========================
__device__ __align__(256) float g_QKV[(size_t)TSEQ * NQKV];
__device__ float g_P  [(size_t)NH * TSEQ * NB];
__device__ float g_QQ [(size_t)NH * TSEQ * NB];
__device__ float g_U  [NB * HK];
__device__ float g_Vv [NB * HK];
__device__ int   g_lut[TSEQ];

__device__ __align__(256) __half g_x16 [(size_t)TSEQ * CDIM];      // x fp16
__device__ __align__(256) __half g_Wt16[(size_t)NQKV * CDIM];      // Wqkv^T fp16
__device__ __align__(256) __half g_Wo16[(size_t)CDIM * CDIM];      // Wo^T fp16
__device__ __align__(256) __half g_Q16 [(size_t)TSEQ * HK];        // pre-scaled by log2(e)
__device__ __align__(256) __half g_K16 [(size_t)TSEQ * HK];
__device__ __align__(256) __half g_Vt16[(size_t)CDIM * TSEQ];      // V^T [1536][2048]
__device__ __align__(256) __half g_O16 [(size_t)TSEQ * CDIM];      // attn out fp16

// ====================== PTX helpers (baseline-PTX only) ====================
__device__ __forceinline__ uint32_t smem_u32(const void* p) {
    uint32_t a;
    asm("{ .reg .u64 t; cvta.to.shared.u64 t, %1; cvt.u32.u64 %0, t; }" : "=r"(a) : "l"(p));
    return a;
}
__device__ __forceinline__ void cp16(uint32_t dst, const void* src) {
    asm volatile("cp.async.cg.shared.global [%0], [%1], 16;" :: "r"(dst), "l"(src));
}
#define CP_COMMIT() asm volatile("cp.async.commit_group;" ::: "memory")
#define CP_WAIT(n)  asm volatile("cp.async.wait_group %0;" :: "n"(n) : "memory")

__device__ __forceinline__ void ldmx4(uint32_t* r, uint32_t addr) {
    asm volatile("ldmatrix.sync.aligned.m8n8.x4.shared.b16 {%0,%1,%2,%3}, [%4];"
        : "=r"(r[0]), "=r"(r[1]), "=r"(r[2]), "=r"(r[3]) : "r"(addr));
}
__device__ __forceinline__ void mma_fp(float* c, const uint32_t* a, const uint32_t* b) {
    asm volatile(
        "mma.sync.aligned.m16n8k16.row.col.f32.f16.f16.f32 "
        "{%0,%1,%2,%3}, {%4,%5,%6,%7}, {%8,%9}, {%0,%1,%2,%3};"
        : "+f"(c[0]), "+f"(c[1]), "+f"(c[2]), "+f"(c[3])
        : "r"(a[0]), "r"(a[1]), "r"(a[2]), "r"(a[3]), "r"(b[0]), "r"(b[1]));
}
__device__ __forceinline__ float ex2f(float x) {
    float r;
    asm("ex2.approx.f32 %0, %1;" : "=f"(r) : "f"(x));
    return r;
}
// swizzled byte offset within a [rows][32 elem] slab (64B rows, 16B chunks)
__device__ __forceinline__ uint32_t swz(int row, int ck) {
    return (uint32_t)(row * 64 + ((ck ^ ((row >> 1) & 3)) << 4));
}

// ====================== single-pass fp16 HMMA GEMM (BK=64) =================
// C[m,n] = sum_k A[m,k]*B[n,k]  (both K-major fp16)
// Stage = 64-k chunk as two 32-k slabs; 3-stage cp.async pipeline.
// QKEPI: fused epilogue writing g_Q16/g_K16 for columns < 1024 (QKV launch)
template <int BN, int MINB, bool QKEPI>
__global__ void __launch_bounds__(256, MINB)
gemm_1p(const __half* __restrict__ A, int lda,
        const __half* __restrict__ B, int ldb,
        float* __restrict__ C, int ldc, int Kd, const float* __restrict__ bias,
        const float* __restrict__ rwb)
{
    extern __shared__ char smem[];
    constexpr int MF = 4, NF = BN / 32;
    constexpr int ASLAB = 128 * 64;      // one 32-k slab of A (bytes)
    constexpr int BSLAB = BN * 64;
    constexpr int ATILE = 2 * ASLAB;     // 64-k stage
    constexpr int BTILE = 2 * BSLAB;
    constexpr int STAGE = ATILE + BTILE;
    constexpr int OFFB  = ATILE;

    const uint32_t sb = smem_u32(smem);
    const int tid = threadIdx.x, lane = tid & 31, wid = tid >> 5;
    const int wm = wid >> 2, wn = wid & 3;
    const int bm = blockIdx.y * 128, bn = blockIdx.x * BN;

    float acc[MF][NF][4];
    #pragma unroll
    for (int i = 0; i < MF; i++)
        #pragma unroll
        for (int j = 0; j < NF; j++)
            #pragma unroll
            for (int t = 0; t < 4; t++) acc[i][j][t] = 0.f;

    auto load_stage = [&](int st, int k0) {
        const uint32_t sa = sb + st * STAGE;
        #pragma unroll
        for (int slab = 0; slab < 2; slab++) {
            #pragma unroll
            for (int r = 0; r < 2; r++) {
                int u = tid + r * 256;
                int row = u >> 2, ck = u & 3;
                size_t go = (size_t)(bm + row) * lda + k0 + slab * 32 + ck * 8;
                cp16(sa + slab * ASLAB + swz(row, ck), A + go);
            }
            #pragma unroll
            for (int r = 0; r < BN / 64; r++) {
                int u = tid + r * 256;
                int row = u >> 2, ck = u & 3;
                size_t go = (size_t)(bn + row) * ldb + k0 + slab * 32 + ck * 8;
                cp16(sa + OFFB + slab * BSLAB + swz(row, ck), B + go);
            }
        }
    };

    auto compute = [&](int st) {
        const uint32_t sa = sb + st * STAGE;
        #pragma unroll
        for (int slab = 0; slab < 2; slab++) {
            #pragma unroll
            for (int ks = 0; ks < 2; ks++) {
                uint32_t ah[MF][4];
                const int g = lane >> 3, rr = lane & 7;
                #pragma unroll
                for (int mf = 0; mf < MF; mf++) {
                    int row = wm * 64 + mf * 16 + rr + (g & 1) * 8;
                    int kc  = ks * 2 + (g >> 1);
                    ldmx4(ah[mf], sa + slab * ASLAB + swz(row, kc));
                }
                uint32_t bf[NF][2];
                #pragma unroll
                for (int p = 0; p < NF / 2; p++) {
                    int row = wn * (BN / 4) + p * 16 + rr + (g >> 1) * 8;
                    int kc  = ks * 2 + (g & 1);
                    uint32_t t[4];
                    ldmx4(t, sa + OFFB + slab * BSLAB + swz(row, kc));
                    bf[2*p][0] = t[0]; bf[2*p][1] = t[1];
                    bf[2*p+1][0] = t[2]; bf[2*p+1][1] = t[3];
                }
                #pragma unroll
                for (int mf = 0; mf < MF; mf++)
                    #pragma unroll
                    for (int nf = 0; nf < NF; nf++)
                        mma_fp(acc[mf][nf], ah[mf], bf[nf]);
            }
        }
    };

    const int NT = Kd >> 6;              // 64-k stages
    load_stage(0, 0);  CP_COMMIT();
    load_stage(1, 64); CP_COMMIT();

    for (int kt = 0; kt < NT; kt++) {
        CP_WAIT(1);
        __syncthreads();
        compute(kt % 3);
        int nk = kt + 2;
        if (nk < NT) load_stage(nk % 3, nk * 64);
        CP_COMMIT();
    }

    #pragma unroll
    for (int mf = 0; mf < MF; mf++) {
        int r0 = bm + wm * 64 + mf * 16 + (lane >> 2);
        #pragma unroll
        for (int nf = 0; nf < NF; nf++) {
            int c0 = bn + wn * (BN / 4) + nf * 8 + (lane & 3) * 2;
            float2 v0 = make_float2(acc[mf][nf][0], acc[mf][nf][1]);
            float2 v1 = make_float2(acc[mf][nf][2], acc[mf][nf][3]);
            if (bias) {
                float b0 = bias[c0], b1 = bias[c0 + 1];
                v0.x += b0; v0.y += b1; v1.x += b0; v1.y += b1;
            }
            // K-region fp32 (cols 512..1023) is dead when QKEPI writes g_K16
            if (!QKEPI || c0 < 512 || c0 >= 1024) {
                *(float2*)&C[(size_t)r0 * ldc + c0]       = v0;
                *(float2*)&C[(size_t)(r0 + 8) * ldc + c0] = v1;
            }
            if (QKEPI && c0 < 1024) {
                if (c0 < 512) {       // Q region: scale + r_w_bias + log2e
                    float b0 = rwb[c0], b1 = rwb[c0 + 1];
                    __half2 q0 = __floats2half2_rn((v0.x * 0.125f + b0) * LOG2E,
                                                   (v0.y * 0.125f + b1) * LOG2E);
                    __half2 q1 = __floats2half2_rn((v1.x * 0.125f + b0) * LOG2E,
                                                   (v1.y * 0.125f + b1) * LOG2E);
                    *(__half2*)&g_Q16[(size_t)r0 * HK + c0]       = q0;
                    *(__half2*)&g_Q16[(size_t)(r0 + 8) * HK + c0] = q1;
                } else {              // K region
                    int ck0 = c0 - 512;
                    *(__half2*)&g_K16[(size_t)r0 * HK + ck0]       = __floats2half2_rn(v0.x, v0.y);
                    *(__half2*)&g_K16[(size_t)(r0 + 8) * HK + ck0] = __floats2half2_rn(v1.x, v1.y);
                }
            }
        }
    }
}

// ====================== fused flash attention ==============================
// CTA = (q-tile of 128 rows, head), 512 threads = 16 warps (4x4 warp grid).
// Fixed-shift softmax (no online max); Q & bias tables pre-scaled by log2(e).
__global__ void __launch_bounds__(512, 1)
flash_kernel()
{
    extern __shared__ char smem[];
    // layout: Q 16384 | K 2x16384 | V 2x49152 | P 32768 | red 2048 |
    //         Pc 128*PCW*4 = 26624 | lutD 4096  -> total 214016
    constexpr uint32_t OQH = 0,      OKB = 16384,  OVB = 49152,
                       OPB = 147456, ORED = 180224, OPT = 182272, OLUTD = 208896;
    const uint32_t sb = smem_u32(smem);
    const int tid = threadIdx.x, lane = tid & 31, wid = tid >> 5;
    const int wm = wid >> 2, wn = wid & 3;                  // 4 x 4 warps
    const int g = lane >> 3, rr = lane & 7, rr4 = lane >> 2, qd = lane & 3;
    const int h = blockIdx.y, bm = blockIdx.x * 128;

    // ---- Q tile load (once): fp16, 2 slabs ----
    #pragma unroll
    for (int r = 0; r < 2; r++) {
        int u = tid + r * 512, slab = u >> 9, rem = u & 511, row = rem >> 2, ck = rem & 3;
        size_t go = (size_t)(bm + row) * HK + h * KDIM + slab * 32 + ck * 8;
        cp16(sb + OQH + slab * 8192 + swz(row, ck), g_Q16 + go);
    }
    auto load_kv = [&](int it, int buf) {
        int kvb = it * 128;
        #pragma unroll
        for (int r = 0; r < 2; r++) {       // K: 2 slabs x 128 rows
            int u = tid + r * 512, slab = u >> 9, rem = u & 511, row = rem >> 2, ck = rem & 3;
            size_t go = (size_t)(kvb + row) * HK + h * KDIM + slab * 32 + ck * 8;
            cp16(sb + OKB + buf * 16384 + slab * 8192 + swz(row, ck), g_K16 + go);
        }
        #pragma unroll
        for (int r = 0; r < 6; r++) {       // V: 4 slabs x 192 rows
            int u = tid + r * 512, slab = u / 768, rem = u - slab * 768;
            int row = rem >> 2, ck = rem & 3;
            size_t go = (size_t)(h * VDIM + row) * TSEQ + kvb + slab * 32 + ck * 8;
            cp16(sb + OVB + buf * 49152 + slab * 12288 + swz(row, ck), g_Vt16 + go);
        }
    };
    load_kv(0, 0);
    CP_COMMIT();

    // ---- combined bias table Pc[r][PCW] = log2e*{P-QQ, P, P+QQ} - 4 ----
    float* Pc = (float*)(smem + OPT);
    for (int i = tid; i < 128 * NB; i += 512) {
        int r = i >> 4, m = i & 15;
        float p  = g_P [((size_t)h * TSEQ + bm + r) * NB + m];
        float qq = g_QQ[((size_t)h * TSEQ + bm + r) * NB + m];
        Pc[r * PCW + m]      = (p - qq) * LOG2E - 4.f;
        Pc[r * PCW + 16 + m] = p * LOG2E - 4.f;
        Pc[r * PCW + 32 + m] = (p + qq) * LOG2E - 4.f;
    }
    // signed-distance LUT: d+2048 -> sel*16 + m  (one byte)
    unsigned char* lutD = (unsigned char*)(smem + OLUTD);
    for (int i = tid; i < 4096; i += 512) {
        int dd = i - 2048;
        int ad = dd < 0 ? -dd : dd;
        if (ad > 2047) ad = 2047;
        int m = g_lut[ad];
        int sel = (dd > 0) ? 32 : ((dd < 0) ? 0 : 16);
        lutD[i] = (unsigned char)(sel + m);
    }
    float* red = (float*)(smem + ORED);

    float accO[2][6][4];
    #pragma unroll
    for (int i = 0; i < 2; i++)
        #pragma unroll
        for (int j = 0; j < 6; j++)
            #pragma unroll
            for (int t = 0; t < 4; t++) accO[i][j][t] = 0.f;
    float lsum[2][2];
    lsum[0][0] = lsum[0][1] = lsum[1][0] = lsum[1][1] = 0.f;

    for (int it = 0; it < 16; it++) {
        CP_WAIT(0);
        __syncthreads();            // loads visible; also P-buffer WAR guard
        if (it < 15) { load_kv(it + 1, (it + 1) & 1); CP_COMMIT(); }
        const uint32_t kb  = sb + OKB + (it & 1) * 16384;
        const uint32_t vbs = sb + OVB + (it & 1) * 49152;

        // ---- phase 1: S = Qw . K^T (fp16, result scaled by log2e) ----
        float accS[2][4][4];
        #pragma unroll
        for (int i = 0; i < 2; i++)
            #pragma unroll
            for (int j = 0; j < 4; j++)
                #pragma unroll
                for (int t = 0; t < 4; t++) accS[i][j][t] = 0.f;

        #pragma unroll
        for (int slab = 0; slab < 2; slab++) {
            #pragma unroll
            for (int ks = 0; ks < 2; ks++) {
                uint32_t ah[2][4];
                #pragma unroll
                for (int mf = 0; mf < 2; mf++) {
                    int row = wm * 32 + mf * 16 + rr + (g & 1) * 8;
                    int kc  = ks * 2 + (g >> 1);
                    ldmx4(ah[mf], sb + OQH + slab * 8192 + swz(row, kc));
                }
                uint32_t bf[4][2];
                #pragma unroll
                for (int p = 0; p < 2; p++) {
                    int row = wn * 32 + p * 16 + rr + (g >> 1) * 8;
                    int kc  = ks * 2 + (g & 1);
                    uint32_t t[4];
                    ldmx4(t, kb + slab * 8192 + swz(row, kc));
                    bf[2*p][0] = t[0]; bf[2*p][1] = t[1];
                    bf[2*p+1][0] = t[2]; bf[2*p+1][1] = t[3];
                }
                #pragma unroll
                for (int mf = 0; mf < 2; mf++)
                    #pragma unroll
                    for (int nf = 0; nf < 4; nf++)
                        mma_fp(accS[mf][nf], ah[mf], bf[nf]);
            }
        }

        // ---- phase 2: bias + exp2 + partial sum + stage P ----
        #pragma unroll
        for (int mf = 0; mf < 2; mf++)
            #pragma unroll
            for (int hf = 0; hf < 2; hf++) {
                int rloc = wm * 32 + mf * 16 + rr4 + hf * 8;
                const float* Pr = Pc + rloc * PCW;
                int base = it * 128 + wn * 32 + qd * 2 - (bm + rloc) + 2048;
                #pragma unroll
                for (int nf = 0; nf < 4; nf++) {
                    int idx = base + nf * 8;
                    float e0 = ex2f(accS[mf][nf][hf*2+0] + Pr[lutD[idx]]);
                    float e1 = ex2f(accS[mf][nf][hf*2+1] + Pr[lutD[idx + 1]]);
                    lsum[mf][hf] += e0 + e1;
                    int jj = wn * 32 + nf * 8 + qd * 2;
                    int slab = jj >> 5, ck = (jj >> 3) & 3;
                    uint32_t off = OPB + slab * 8192 + rloc * 64 +
                                   ((ck ^ ((rloc >> 1) & 3)) << 4) + (jj & 7) * 2;
                    *(__half2*)(smem + off) = __floats2half2_rn(e0, e1);
                }
            }
        __syncthreads();                        // P staging visible

        // ---- phase 3: O += P . V^T ----
        #pragma unroll
        for (int slab = 0; slab < 4; slab++) {
            #pragma unroll
            for (int ks = 0; ks < 2; ks++) {
                uint32_t pa[2][4];
                #pragma unroll
                for (int mf = 0; mf < 2; mf++) {
                    int row = wm * 32 + mf * 16 + rr + (g & 1) * 8;
                    int kc  = ks * 2 + (g >> 1);
                    ldmx4(pa[mf], sb + OPB + slab * 8192 + swz(row, kc));
                }
                uint32_t vf[6][2];
                #pragma unroll
                for (int p = 0; p < 3; p++) {
                    int row = wn * 48 + p * 16 + rr + (g >> 1) * 8;
                    int kc  = ks * 2 + (g & 1);
                    uint32_t t[4];
                    ldmx4(t, vbs + slab * 12288 + swz(row, kc));
                    vf[2*p][0] = t[0]; vf[2*p][1] = t[1];
                    vf[2*p+1][0] = t[2]; vf[2*p+1][1] = t[3];
                }
                #pragma unroll
                for (int mf = 0; mf < 2; mf++)
                    #pragma unroll
                    for (int nf = 0; nf < 6; nf++)
                        mma_fp(accO[mf][nf], pa[mf], vf[nf]);
            }
        }
        // no end-of-iteration sync: loop-top sync orders P rewrite vs reads
    }

    // ---- final: reduce row sums, normalize, write fp16 O ----
    #pragma unroll
    for (int mf = 0; mf < 2; mf++)
        #pragma unroll
        for (int hf = 0; hf < 2; hf++) {
            float s = lsum[mf][hf];
            s += __shfl_xor_sync(0xffffffffu, s, 1);
            s += __shfl_xor_sync(0xffffffffu, s, 2);
            if (qd == 0) {
                int rloc = wm * 32 + mf * 16 + rr4 + hf * 8;
                red[rloc * 4 + wn] = s;
            }
        }
    __syncthreads();
    float inv[2][2];
    #pragma unroll
    for (int mf = 0; mf < 2; mf++)
        #pragma unroll
        for (int hf = 0; hf < 2; hf++) {
            int rloc = wm * 32 + mf * 16 + rr4 + hf * 8;
            inv[mf][hf] = 1.f / (red[rloc*4+0] + red[rloc*4+1] +
                                 red[rloc*4+2] + red[rloc*4+3]);
        }
    #pragma unroll
    for (int mf = 0; mf < 2; mf++) {
        int r0 = bm + wm * 32 + mf * 16 + rr4;
        #pragma unroll
        for (int nf = 0; nf < 6; nf++) {
            int c0 = h * VDIM + wn * 48 + nf * 8 + qd * 2;
            __half2 hh0 = __floats2half2_rn(accO[mf][nf][0] * inv[mf][0],
                                            accO[mf][nf][1] * inv[mf][0]);
            __half2 hh1 = __floats2half2_rn(accO[mf][nf][2] * inv[mf][1],
                                            accO[mf][nf][3] * inv[mf][1]);
            *(__half2*)&g_O16[(size_t)r0 * CDIM + c0]       = hh0;
            *(__half2*)&g_O16[(size_t)(r0 + 8) * CDIM + c0] = hh1;
        }
    }
}

// ====================== fused prep kernels =================================
// prep1: z 0-3 = weight transposes, z=4 = positional setup, z=5 = x->fp16
__global__ void prep1_kernel(const float* __restrict__ Wq, const float* __restrict__ Wk,
                             const float* __restrict__ Wv, const float* __restrict__ Wo,
                             const float* __restrict__ Wr, const float* __restrict__ x)
{
    const int tid = threadIdx.x;
    const int z = blockIdx.z;

    if (z < 4) {
        const float* src; __half* dst; int sld, drow0;
        switch (z) {
            case 0:  src = Wq; dst = g_Wt16; sld = HK;   drow0 = 0;    break;
            case 1:  src = Wk; dst = g_Wt16; sld = HK;   drow0 = 512;  break;
            case 2:  src = Wv; dst = g_Wt16; sld = CDIM; drow0 = 1024; break;
            default: src = Wo; dst = g_Wo16; sld = CDIM; drow0 = 0;    break;
        }
        int n0 = blockIdx.x * 32, k0 = blockIdx.y * 32;
        if (n0 >= sld) return;
        __shared__ float t[32][33];
        int tx = tid & 31, ty = tid >> 5;
        for (int i = ty; i < 32; i += 8)
            t[i][tx] = src[(size_t)(k0 + i) * sld + n0 + tx];
        __syncthreads();
        for (int i = ty; i < 32; i += 8)
            dst[(size_t)(drow0 + n0 + i) * CDIM + k0 + tx] = __float2half(t[tx][i]);
    } else if (z == 4) {
        if (blockIdx.x != 0 || blockIdx.y != 0) return;
        __shared__ float cw[NB];
        if (tid == 0) {
            float pr = expf(logf((float)(TSEQ + 1)) / (float)NB);
            for (int i = 0; i < NB; i++) cw[i] = powf(pr, (float)(i + 1)) - 1.0f;
        }
        __syncthreads();
        for (int d = tid; d < TSEQ; d += 256) {
            int m = 0;
            #pragma unroll
            for (int i = 0; i < NB; i++)
                if (cw[i] <= (float)d) m++;
            g_lut[d] = m;
        }
        for (int c = tid; c < HK; c += 256) {
            float s = 0.f, s2 = 0.f;
            for (int i = NB - 1; i >= 0; i--) {
                s  += Wr[i * HK + c];
                s2 += Wr[(NB + i) * HK + c];
                g_U [i * HK + c] = s;
                g_Vv[i * HK + c] = s2;
            }
        }
    } else {
        // x -> fp16 (vectorized float2 -> half2), grid-stride
        const float2* xv = (const float2*)x;
        __half2* dv = (__half2*)g_x16;
        size_t n2 = (size_t)TSEQ * CDIM / 2;
        size_t base = ((size_t)blockIdx.y * 48 + blockIdx.x) * 256 + tid;
        for (size_t i = base; i < n2; i += (size_t)48 * 48 * 256) {
            float2 v = xv[i];
            dv[i] = __floats2half2_rn(v.x, v.y);
        }
    }
}

// prep2 (after QKV GEMM): z=0 V^T transpose, z=1 pq tables
__global__ void prep2_kernel(const float* __restrict__ rrb)
{
    const int tid = threadIdx.x;
    const int z = blockIdx.z;
    const int bid = blockIdx.y * 48 + blockIdx.x;

    if (z == 0) {
        // V^T: [2048 tokens][1536 dims(fp32 at QKV col 1024+)] -> [1536][2048] fp16
        __shared__ float t[32][33];
        int n0 = blockIdx.x * 32, k0 = blockIdx.y * 32;   // x<48 dims, y<64 tokens
        int tx = tid & 31, ty = tid >> 5;
        const float* src = g_QKV + 1024;
        for (int i = ty; i < 32; i += 8)
            t[i][tx] = src[(size_t)(k0 + i) * NQKV + n0 + tx];
        __syncthreads();
        for (int i = ty; i < 32; i += 8)
            g_Vt16[(size_t)(n0 + i) * TSEQ + k0 + tx] = __float2half(t[tx][i]);
    } else {
        // pq: 2 q-rows per 256-thread block
        if (bid >= TSEQ / 2) return;
        __shared__ float qs[2][HK];
        int sub = tid >> 7, t = tid & 127;
        int q = bid * 2 + sub;
        for (int i = t; i < HK; i += 128)
            qs[sub][i] = g_QKV[(size_t)q * NQKV + i] * 0.125f + rrb[i];
        __syncthreads();
        int h = t >> 4, m = t & 15;
        const float* u  = g_U  + m * HK + h * KDIM;
        const float* v2 = g_Vv + m * HK + h * KDIM;
        const float* qh = qs[sub] + h * KDIM;
        float p = 0.f, pq = 0.f;
        #pragma unroll 8
        for (int k = 0; k < KDIM; k++) {
            p  = fmaf(qh[k], u[k],  p);
            pq = fmaf(qh[k], v2[k], pq);
        }
        size_t idx = ((size_t)h * TSEQ + q) * NB + m;
        g_P[idx]  = p;
        g_QQ[idx] = pq;
    }
}

// ====================== launch =============================================
extern "C" void kernel_launch(void* const* d_in, const int* in_sizes, int n_in,
                              void* d_out, int out_size)
{
    const float* x   = (const float*)d_in[0];
    const float* Wq  = (const float*)d_in[1];
    const float* Wk  = (const float*)d_in[2];
    const float* Wv  = (const float*)d_in[3];
    const float* Wr  = (const float*)d_in[4];
    const float* rwb = (const float*)d_in[5];
    const float* rrb = (const float*)d_in[6];
    const float* Wo  = (const float*)d_in[7];
    const float* bo  = (const float*)d_in[8];
    float* out = (float*)d_out;

    float* QKV;
    __half *x16, *Wt16, *Wo16, *O16;
    cudaGetSymbolAddress((void**)&QKV,  g_QKV);
    cudaGetSymbolAddress((void**)&x16,  g_x16);
    cudaGetSymbolAddress((void**)&Wt16, g_Wt16);
    cudaGetSymbolAddress((void**)&Wo16, g_Wo16);
    cudaGetSymbolAddress((void**)&O16,  g_O16);

    constexpr int SMEM_128   = 3 * (2 * 8192 + 2 * 8192);   // 98304; 2/SM = 196608
    constexpr int SMEM_64    = 3 * (2 * 8192 + 2 * 4096);   // 73728; 2/SM = 147456
    constexpr int SMEM_FLASH = 214528;
    cudaFuncSetAttribute((const void*)gemm_1p<128, 2, true>,
                         cudaFuncAttributeMaxDynamicSharedMemorySize, SMEM_128);
    cudaFuncSetAttribute((const void*)gemm_1p<64, 2, false>,
                         cudaFuncAttributeMaxDynamicSharedMemorySize, SMEM_64);
    cudaFuncSetAttribute((const void*)flash_kernel,
                         cudaFuncAttributeMaxDynamicSharedMemorySize, SMEM_FLASH);

    // --- fused preprocessing: weight transposes + setup + x conversion ---
    prep1_kernel<<<dim3(48, 48, 6), 256>>>(Wq, Wk, Wv, Wo, Wr, x);

    // --- fused QKV projection + Q16/K16 epilogue (fp16 single-pass, BK=64) ---
    gemm_1p<128, 2, true><<<dim3(NQKV / 128, TSEQ / 128, 1), 256, SMEM_128>>>(
        x16, CDIM, Wt16, CDIM, QKV, NQKV, CDIM, nullptr, rwb);

    // --- fused post-QKV prep: V^T + pq tables ---
    prep2_kernel<<<dim3(48, 64, 2), 256>>>(rrb);

    // --- fused attention: 128-row q-tiles ---
    flash_kernel<<<dim3(TSEQ / 128, NH), 512, SMEM_FLASH>>>();

    // --- output projection: 128x64 tiles (384 CTAs, 2 CTAs/SM, BK=64) ---
    gemm_1p<64, 2, false><<<dim3(CDIM / 64, TSEQ / 128, 1), 256, SMEM_64>>>(
        O16, CDIM, Wo16, CDIM, out, CDIM, CDIM, bo, nullptr);
}